// round 10
// baseline (speedup 1.0000x reference)
#include <cuda_runtime.h>
#include <cuda_bf16.h>
#include <cstdint>

#define T_ 4
#define B_ 8
#define C_ 512
#define D_ 768
#define H_ 8
#define HD_ 96
#define MKV_ 192
#define NCAT_ 1152            // 768 (q) + 192 (k) + 192 (v)
#define BC_ 4096              // B*C
#define M_ 16384              // T*B*C
#define BCD_ 3145728          // B*C*D

// ---------------- scratch (device globals: no allocation allowed) ----------
__device__ __nv_bfloat16 g_xs[M_ * D_];        // proj_lif spikes (exact 0/1)
__device__ __nv_bfloat16 g_Whi[NCAT_ * D_];    // concat [q_w; k_w; v_w] hi
__device__ __nv_bfloat16 g_Wlo[NCAT_ * D_];    // lo residual
__device__ __nv_bfloat16 g_WOhi[D_ * D_];
__device__ __nv_bfloat16 g_WOlo[D_ * D_];
__device__ float         g_pre[M_ * NCAT_];    // pre-activation of q/k/v proj
__device__ int8_t        g_sp8[M_ * NCAT_];    // q/k/v spikes (int8 0/1, exact)
__device__ int8_t        g_vT8[T_ * B_ * MKV_ * C_]; // v spikes transposed (d-major)
__device__ __nv_bfloat16 g_ahi[M_ * D_];       // attention output hi
__device__ __nv_bfloat16 g_alo[M_ * D_];       // attention output lo

// ---------------- helpers ----------------
__device__ __forceinline__ uint32_t smem_u32(const void* p) {
    uint32_t a;
    asm("{ .reg .u64 t; cvta.to.shared.u64 t, %1; cvt.u32.u64 %0, t; }" : "=r"(a) : "l"(p));
    return a;
}
__device__ __forceinline__ void mma_bf16(float* c, const uint32_t* a, const uint32_t* b) {
    asm volatile(
        "mma.sync.aligned.m16n8k16.row.col.f32.bf16.bf16.f32 "
        "{%0,%1,%2,%3},{%4,%5,%6,%7},{%8,%9},{%0,%1,%2,%3};\n"
        : "+f"(c[0]), "+f"(c[1]), "+f"(c[2]), "+f"(c[3])
        : "r"(a[0]), "r"(a[1]), "r"(a[2]), "r"(a[3]), "r"(b[0]), "r"(b[1]));
}
__device__ __forceinline__ void mma_s8(int32_t* c, const uint32_t* a, const uint32_t* b) {
    asm volatile(
        "mma.sync.aligned.m16n8k32.row.col.s32.s8.s8.s32 "
        "{%0,%1,%2,%3},{%4,%5,%6,%7},{%8,%9},{%0,%1,%2,%3};\n"
        : "+r"(c[0]), "+r"(c[1]), "+r"(c[2]), "+r"(c[3])
        : "r"(a[0]), "r"(a[1]), "r"(a[2]), "r"(a[3]), "r"(b[0]), "r"(b[1]));
}
__device__ __forceinline__ void ldsm_x4(uint32_t* r, uint32_t addr) {
    asm volatile("ldmatrix.sync.aligned.m8n8.x4.shared.b16 {%0,%1,%2,%3}, [%4];"
        : "=r"(r[0]), "=r"(r[1]), "=r"(r[2]), "=r"(r[3]) : "r"(addr));
}
__device__ __forceinline__ void ldsm_x2(uint32_t* r, uint32_t addr) {
    asm volatile("ldmatrix.sync.aligned.m8n8.x2.shared.b16 {%0,%1}, [%2];"
        : "=r"(r[0]), "=r"(r[1]) : "r"(addr));
}
__device__ __forceinline__ void cpa16(uint32_t dst, const void* src) {
    asm volatile("cp.async.ca.shared.global [%0], [%1], 16;" :: "r"(dst), "l"(src));
}
#define CP_COMMIT()  asm volatile("cp.async.commit_group;" ::: "memory")
#define CP_WAIT(n)   asm volatile("cp.async.wait_group %0;" :: "n"(n) : "memory")

// ---------------- kernel 1: split weights into bf16 hi/lo ----------------
__global__ void pack_w_k(const float* __restrict__ qw, const float* __restrict__ kw,
                         const float* __restrict__ vw, const float* __restrict__ wow) {
    int i = blockIdx.x * 256 + threadIdx.x;
    if (i < NCAT_ * D_) {
        int n = i / D_, k = i - n * D_;
        float w;
        if (n < D_)            w = qw[i];
        else if (n < D_ + MKV_) w = kw[(n - D_) * D_ + k];
        else                    w = vw[(n - D_ - MKV_) * D_ + k];
        __nv_bfloat16 hi = __float2bfloat16(w);
        g_Whi[i] = hi;
        g_Wlo[i] = __float2bfloat16(w - __bfloat162float(hi));
    }
    if (i < D_ * D_) {
        float w = wow[i];
        __nv_bfloat16 hi = __float2bfloat16(w);
        g_WOhi[i] = hi;
        g_WOlo[i] = __float2bfloat16(w - __bfloat162float(hi));
    }
}

// ---------------- kernel 2: LIF on x -> xs spikes (bf16 exact) -------------
__global__ void lif_x_k(const float* __restrict__ x) {
    int i = blockIdx.x * 256 + threadIdx.x;
    if (i >= BCD_) return;
    float v = 0.f;
#pragma unroll
    for (int t = 0; t < T_; t++) {
        v = v * 0.5f + x[t * BCD_ + i];
        bool s = (v >= 1.0f);
        g_xs[t * BCD_ + i] = __float2bfloat16(s ? 1.f : 0.f);
        if (s) v = 0.f;
    }
}

// ---------------- kernel 3: projection GEMM  pre = xs @ [Wq;Wk;Wv]^T -------
// r8 (WIN): K-chunk 32, 80B stride, ldmatrix, cp.async.ca double buffer.
#define PSTR 40                 // smem row stride, bf16 units
#define PSTRB 80                // ... bytes
#define PTILE (128 * PSTR)      // tile bf16 units
#define PTILEB (128 * PSTRB)    // tile bytes (10240)
#define PSTGB (3 * PTILEB)      // 30720
#define NCH 24                  // K=768 / 32
__global__ void __launch_bounds__(256)
gemm_proj_k() {
    extern __shared__ __nv_bfloat16 smp[];
    uint32_t sbase = smem_u32(smp);
    int tid = threadIdx.x;
    int lane = tid & 31, warp = tid >> 5;
    int gid = lane >> 2, tig = lane & 3;
    int wm = (warp >> 2) * 64, wn = (warp & 3) * 32;
    int m0 = blockIdx.y * 128, n0 = blockIdx.x * 128;

    uint32_t a_off = (wm + (lane & 15)) * PSTRB + (lane >> 4) * 16;
    uint32_t b_off = (wn + ((lane >> 4) << 3) + (lane & 7)) * PSTRB + ((lane >> 3) & 1) * 16;

    float acc[4][4][4];
#pragma unroll
    for (int a = 0; a < 4; a++)
#pragma unroll
        for (int b = 0; b < 4; b++)
#pragma unroll
            for (int c = 0; c < 4; c++) acc[a][b][c] = 0.f;

    int r0 = tid >> 2, c4b = (tid & 3) * 16;

#pragma unroll
    for (int it = 0; it < 2; it++) {
        int rr = r0 + it * 64;
        cpa16(sbase + rr * PSTRB + c4b,
              (const char*)(g_xs + (size_t)(m0 + rr) * D_) + c4b);
        cpa16(sbase + PTILEB + rr * PSTRB + c4b,
              (const char*)(g_Whi + (size_t)(n0 + rr) * D_) + c4b);
        cpa16(sbase + 2 * PTILEB + rr * PSTRB + c4b,
              (const char*)(g_Wlo + (size_t)(n0 + rr) * D_) + c4b);
    }
    CP_COMMIT();

    for (int c = 0; c < NCH; c++) {
        if (c + 1 < NCH) {
            uint32_t st = ((c + 1) & 1) * PSTGB;
            int kb = (c + 1) * 64;
#pragma unroll
            for (int it = 0; it < 2; it++) {
                int rr = r0 + it * 64;
                cpa16(sbase + st + rr * PSTRB + c4b,
                      (const char*)(g_xs + (size_t)(m0 + rr) * D_) + kb + c4b);
                cpa16(sbase + st + PTILEB + rr * PSTRB + c4b,
                      (const char*)(g_Whi + (size_t)(n0 + rr) * D_) + kb + c4b);
                cpa16(sbase + st + 2 * PTILEB + rr * PSTRB + c4b,
                      (const char*)(g_Wlo + (size_t)(n0 + rr) * D_) + kb + c4b);
            }
            CP_COMMIT();
            CP_WAIT(1);
        } else {
            CP_WAIT(0);
        }
        __syncthreads();
        uint32_t off = (c & 1) * PSTGB;
        uint32_t a_base = sbase + off + a_off;
        uint32_t bh_base = sbase + off + PTILEB + b_off;
        uint32_t bl_base = sbase + off + 2 * PTILEB + b_off;
#pragma unroll
        for (int kk = 0; kk < 2; kk++) {
            uint32_t af[4][4], bh[2][4], bl[2][4];
#pragma unroll
            for (int mt = 0; mt < 4; mt++)
                ldsm_x4(af[mt], a_base + mt * (16 * PSTRB) + kk * 32);
#pragma unroll
            for (int j = 0; j < 2; j++) {
                ldsm_x4(bh[j], bh_base + j * (16 * PSTRB) + kk * 32);
                ldsm_x4(bl[j], bl_base + j * (16 * PSTRB) + kk * 32);
            }
#pragma unroll
            for (int nt = 0; nt < 4; nt++) {
                const uint32_t* bhp = &bh[nt >> 1][(nt & 1) * 2];
                const uint32_t* blp = &bl[nt >> 1][(nt & 1) * 2];
#pragma unroll
                for (int mt = 0; mt < 4; mt++) {
                    mma_bf16(acc[mt][nt], af[mt], bhp);
                    mma_bf16(acc[mt][nt], af[mt], blp);
                }
            }
        }
        __syncthreads();
    }
#pragma unroll
    for (int mt = 0; mt < 4; mt++)
#pragma unroll
        for (int nt = 0; nt < 4; nt++) {
            int r = m0 + wm + mt * 16 + gid;
            int c = n0 + wn + nt * 8 + tig * 2;
            *(float2*)(g_pre + (size_t)r * NCAT_ + c) = make_float2(acc[mt][nt][0], acc[mt][nt][1]);
            *(float2*)(g_pre + (size_t)(r + 8) * NCAT_ + c) = make_float2(acc[mt][nt][2], acc[mt][nt][3]);
        }
}

// ---------------- kernel 4: LIF on projections -> int8 spikes (coalesced) --
__global__ void lif_proj8_k() {
    int i = blockIdx.x * 256 + threadIdx.x;          // one per (bc, n4)
    if (i >= BC_ * (NCAT_ / 4)) return;
    int bc = i / (NCAT_ / 4), n4 = (i - bc * (NCAT_ / 4)) * 4;
    float v[4] = {0.f, 0.f, 0.f, 0.f};
#pragma unroll
    for (int t = 0; t < T_; t++) {
        size_t row = (size_t)(t * BC_ + bc);
        float4 p = *(const float4*)(g_pre + row * NCAT_ + n4);
        float pv[4] = {p.x, p.y, p.z, p.w};
        uint32_t w = 0u;
#pragma unroll
        for (int j = 0; j < 4; j++) {
            v[j] = v[j] * 0.5f + pv[j];
            bool sp = (v[j] >= 1.0f);
            if (sp) { w |= 1u << (j * 8); v[j] = 0.f; }
        }
        *(uint32_t*)(g_sp8 + row * NCAT_ + n4) = w;
    }
}

// ---------------- kernel 5: transpose v spikes (coalesced tiles, int8) -----
__global__ void transpose_v_k() {
    __shared__ int8_t smT[32][33];
    int c0 = blockIdx.x * 32, n0 = blockIdx.y * 32, z = blockIdx.z; // z = t*B+b
    int t = z >> 3, b = z & 7;
    int tx = threadIdx.x, ty = threadIdx.y;
#pragma unroll
    for (int j = 0; j < 4; j++) {
        int r = ty + j * 8;
        smT[r][tx] = g_sp8[(size_t)(t * BC_ + b * C_ + c0 + r) * NCAT_ + (D_ + MKV_) + n0 + tx];
    }
    __syncthreads();
#pragma unroll
    for (int j = 0; j < 4; j++) {
        int nv = ty + j * 8;
        g_vT8[((size_t)z * MKV_ + n0 + nv) * C_ + c0 + tx] = smT[tx][nv];
    }
}

// ---------------- kernel 6: int8 attention, exact, cp.async + ldmatrix -----
// smem bytes: Q[128x112]=14336 | K0,K1[128x112] | V0,V1[96x144] | S[128x144]
#define QSTB 112
#define VSTB 144
#define SSTB 144
#define AOFFK0 14336
#define AOFFV0 (14336 + 2 * 14336)          // 43008
#define AOFFS  (AOFFV0 + 2 * 13824)         // 70656
#define ATTN_SMEM_B (AOFFS + 128 * SSTB)    // 89088
__global__ void __launch_bounds__(256)
attn_k() {
    extern __shared__ char smA[];
    uint32_t sb = smem_u32(smA);
    char* sS = smA + AOFFS;

    int tid = threadIdx.x, lane = tid & 31, warp = tid >> 5;
    int gid = lane >> 2, tig = lane & 3;
    int wm = (warp >> 2) * 64;
    int wn1 = (warp & 3) * 32;  // key cols in mma1
    int wn2 = (warp & 3) * 24;  // d cols in mma2
    int qb = blockIdx.x;
    int tbh = blockIdx.y;
    int h = tbh & 7, tb = tbh >> 3;
    int kvh = h >> 2;
    int qcol = h * HD_;
    int kcol = D_ + kvh * HD_;
    int rowbase = tb * C_;

    // ldmatrix lane-address formulas (int8: 16B-group addressing identical to bf16)
    uint32_t q_base = sb + (wm + (lane & 15)) * QSTB + (lane >> 4) * 16;
    uint32_t k_off = (wn1 + ((lane >> 4) << 3) + (lane & 7)) * QSTB + ((lane >> 3) & 1) * 16;
    uint32_t s_base = sb + AOFFS + (wm + (lane & 15)) * SSTB + (lane >> 4) * 16;
    uint32_t v4_off = (wn2 + ((lane >> 4) << 3) + (lane & 7)) * VSTB + ((lane >> 3) & 1) * 16;
    uint32_t v2_off = (wn2 + 16 + (lane & 7)) * VSTB + ((lane >> 3) & 1) * 16;
    uint32_t k_stage[2] = { sb + AOFFK0 + k_off, sb + AOFFK0 + 14336 + k_off };
    uint32_t v4_stage[2] = { sb + AOFFV0 + v4_off, sb + AOFFV0 + 13824 + v4_off };
    uint32_t v2_stage[2] = { sb + AOFFV0 + v2_off, sb + AOFFV0 + 13824 + v2_off };

    // prologue: Q + K(kc=0) + V(kc=0), one commit group (rows of 96B = 6x16B)
#pragma unroll
    for (int it = 0; it < 3; it++) {
        int idx = tid + it * 256;
        int r = idx / 6, c = idx % 6;
        cpa16(sb + r * QSTB + c * 16,
              (const char*)(g_sp8 + (size_t)(rowbase + qb * 128 + r) * NCAT_ + qcol) + c * 16);
    }
#pragma unroll
    for (int it = 0; it < 3; it++) {
        int idx = tid + it * 256;
        int r = idx / 6, c = idx % 6;
        cpa16(sb + AOFFK0 + r * QSTB + c * 16,
              (const char*)(g_sp8 + (size_t)(rowbase + r) * NCAT_ + kcol) + c * 16);
    }
#pragma unroll
    for (int it = 0; it < 3; it++) {
        int idx = tid + it * 256;
        int r = idx >> 3, c = idx & 7;
        cpa16(sb + AOFFV0 + r * VSTB + c * 16,
              (const char*)(g_vT8 + (size_t)(tb * MKV_ + kvh * HD_ + r) * C_) + c * 16);
    }
    CP_COMMIT();

    int32_t acc2[4][3][4];
#pragma unroll
    for (int a = 0; a < 4; a++)
#pragma unroll
        for (int b = 0; b < 3; b++)
#pragma unroll
            for (int c = 0; c < 4; c++) acc2[a][b][c] = 0;

    for (int kc = 0; kc < 4; kc++) {
        if (kc + 1 < 4) {
            uint32_t kst = sb + AOFFK0 + ((kc + 1) & 1) * 14336;
            uint32_t vst = sb + AOFFV0 + ((kc + 1) & 1) * 13824;
#pragma unroll
            for (int it = 0; it < 3; it++) {
                int idx = tid + it * 256;
                int r = idx / 6, c = idx % 6;
                cpa16(kst + r * QSTB + c * 16,
                      (const char*)(g_sp8 + (size_t)(rowbase + (kc + 1) * 128 + r) * NCAT_ + kcol) + c * 16);
            }
#pragma unroll
            for (int it = 0; it < 3; it++) {
                int idx = tid + it * 256;
                int r = idx >> 3, c = idx & 7;
                cpa16(vst + r * VSTB + c * 16,
                      (const char*)(g_vT8 + (size_t)(tb * MKV_ + kvh * HD_ + r) * C_ + (kc + 1) * 128) + c * 16);
            }
            CP_COMMIT();
            CP_WAIT(1);
        } else {
            CP_WAIT(0);
        }
        __syncthreads();
        int st = kc & 1;

        // mma1: counts = q @ k^T  (128x128, K=96) s8, 3 k32 steps — exact
        int32_t acc1[4][4][4];
#pragma unroll
        for (int a = 0; a < 4; a++)
#pragma unroll
            for (int b = 0; b < 4; b++)
#pragma unroll
                for (int c = 0; c < 4; c++) acc1[a][b][c] = 0;
#pragma unroll
        for (int kk = 0; kk < 3; kk++) {
            uint32_t af[4][4], bk[2][4];
#pragma unroll
            for (int mt = 0; mt < 4; mt++)
                ldsm_x4(af[mt], q_base + mt * (16 * QSTB) + kk * 32);
#pragma unroll
            for (int j = 0; j < 2; j++)
                ldsm_x4(bk[j], k_stage[st] + j * (16 * QSTB) + kk * 32);
#pragma unroll
            for (int nt = 0; nt < 4; nt++) {
                const uint32_t* bb = &bk[nt >> 1][(nt & 1) * 2];
#pragma unroll
                for (int mt = 0; mt < 4; mt++) mma_s8(acc1[mt][nt], af[mt], bb);
            }
        }
        // store counts as int8 (exact: <=96)
#pragma unroll
        for (int mt = 0; mt < 4; mt++)
#pragma unroll
            for (int nt = 0; nt < 4; nt++) {
                int r = wm + mt * 16 + gid;
                int cc = wn1 + nt * 8 + tig * 2;
                *(uint16_t*)(sS + r * SSTB + cc) =
                    (uint16_t)((acc1[mt][nt][0] & 0xFF) | ((acc1[mt][nt][1] & 0xFF) << 8));
                *(uint16_t*)(sS + (r + 8) * SSTB + cc) =
                    (uint16_t)((acc1[mt][nt][2] & 0xFF) | ((acc1[mt][nt][3] & 0xFF) << 8));
            }
        __syncthreads();

        // mma2: acc2 += counts @ v  (128x96, K=128) s8, 4 k32 steps — exact
#pragma unroll
        for (int kk = 0; kk < 4; kk++) {
            uint32_t af[4][4], bv[6];
#pragma unroll
            for (int mt = 0; mt < 4; mt++)
                ldsm_x4(af[mt], s_base + mt * (16 * SSTB) + kk * 32);
            ldsm_x4(bv, v4_stage[st] + kk * 32);       // nt0, nt1
            ldsm_x2(bv + 4, v2_stage[st] + kk * 32);   // nt2
#pragma unroll
            for (int nt = 0; nt < 3; nt++) {
                const uint32_t* bb = &bv[nt * 2];
#pragma unroll
                for (int mt = 0; mt < 4; mt++) mma_s8(acc2[mt][nt], af[mt], bb);
            }
        }
        __syncthreads();
    }

    // epilogue: scale by 0.1, hi/lo split for the wo GEMM (same values as bf16 path)
#pragma unroll
    for (int mt = 0; mt < 4; mt++)
#pragma unroll
        for (int nt = 0; nt < 3; nt++) {
            int r = rowbase + qb * 128 + wm + mt * 16 + gid;
            int cb = qcol + wn2 + nt * 8 + tig * 2;
#pragma unroll
            for (int half = 0; half < 2; half++) {
                int rr = r + half * 8;
                float v0 = 0.1f * (float)acc2[mt][nt][half * 2 + 0];
                float v1 = 0.1f * (float)acc2[mt][nt][half * 2 + 1];
                __nv_bfloat162 hi2, lo2;
                hi2.x = __float2bfloat16(v0);
                hi2.y = __float2bfloat16(v1);
                lo2.x = __float2bfloat16(v0 - __bfloat162float(hi2.x));
                lo2.y = __float2bfloat16(v1 - __bfloat162float(hi2.y));
                *(__nv_bfloat162*)(g_ahi + (size_t)rr * D_ + cb) = hi2;
                *(__nv_bfloat162*)(g_alo + (size_t)rr * D_ + cb) = lo2;
            }
        }
}

// ---------------- kernel 7: output GEMM  d_out = attn @ wo^T ----------------
// r8 (WIN): cp.async.ca double buffer; A/B hi/lo -> 3 MMAs per k-step.
#define WSTGB (4 * PTILEB)     // 40960
__global__ void __launch_bounds__(256)
gemm_wo_k(float* __restrict__ out) {
    extern __shared__ __nv_bfloat16 smw[];
    uint32_t sbase = smem_u32(smw);
    int tid = threadIdx.x;
    int lane = tid & 31, warp = tid >> 5;
    int gid = lane >> 2, tig = lane & 3;
    int wm = (warp >> 2) * 64, wn = (warp & 3) * 32;
    int m0 = blockIdx.y * 128, n0 = blockIdx.x * 128;

    uint32_t a_off = (wm + (lane & 15)) * PSTRB + (lane >> 4) * 16;
    uint32_t b_off = (wn + ((lane >> 4) << 3) + (lane & 7)) * PSTRB + ((lane >> 3) & 1) * 16;

    float acc[4][4][4];
#pragma unroll
    for (int a = 0; a < 4; a++)
#pragma unroll
        for (int b = 0; b < 4; b++)
#pragma unroll
            for (int c = 0; c < 4; c++) acc[a][b][c] = 0.f;

    int r0 = tid >> 2, c4b = (tid & 3) * 16;

#pragma unroll
    for (int it = 0; it < 2; it++) {
        int rr = r0 + it * 64;
        cpa16(sbase + rr * PSTRB + c4b,
              (const char*)(g_ahi + (size_t)(m0 + rr) * D_) + c4b);
        cpa16(sbase + PTILEB + rr * PSTRB + c4b,
              (const char*)(g_alo + (size_t)(m0 + rr) * D_) + c4b);
        cpa16(sbase + 2 * PTILEB + rr * PSTRB + c4b,
              (const char*)(g_WOhi + (size_t)(n0 + rr) * D_) + c4b);
        cpa16(sbase + 3 * PTILEB + rr * PSTRB + c4b,
              (const char*)(g_WOlo + (size_t)(n0 + rr) * D_) + c4b);
    }
    CP_COMMIT();

    for (int c = 0; c < NCH; c++) {
        if (c + 1 < NCH) {
            uint32_t st = ((c + 1) & 1) * WSTGB;
            int kb = (c + 1) * 64;
#pragma unroll
            for (int it = 0; it < 2; it++) {
                int rr = r0 + it * 64;
                cpa16(sbase + st + rr * PSTRB + c4b,
                      (const char*)(g_ahi + (size_t)(m0 + rr) * D_) + kb + c4b);
                cpa16(sbase + st + PTILEB + rr * PSTRB + c4b,
                      (const char*)(g_alo + (size_t)(m0 + rr) * D_) + kb + c4b);
                cpa16(sbase + st + 2 * PTILEB + rr * PSTRB + c4b,
                      (const char*)(g_WOhi + (size_t)(n0 + rr) * D_) + kb + c4b);
                cpa16(sbase + st + 3 * PTILEB + rr * PSTRB + c4b,
                      (const char*)(g_WOlo + (size_t)(n0 + rr) * D_) + kb + c4b);
            }
            CP_COMMIT();
            CP_WAIT(1);
        } else {
            CP_WAIT(0);
        }
        __syncthreads();
        uint32_t off = (c & 1) * WSTGB;
        uint32_t ah_base = sbase + off + a_off;
        uint32_t al_base = sbase + off + PTILEB + a_off;
        uint32_t bh_base = sbase + off + 2 * PTILEB + b_off;
        uint32_t bl_base = sbase + off + 3 * PTILEB + b_off;
#pragma unroll
        for (int kk = 0; kk < 2; kk++) {
            uint32_t afh[4][4], afl[4][4], bh[2][4], bl[2][4];
#pragma unroll
            for (int mt = 0; mt < 4; mt++) {
                ldsm_x4(afh[mt], ah_base + mt * (16 * PSTRB) + kk * 32);
                ldsm_x4(afl[mt], al_base + mt * (16 * PSTRB) + kk * 32);
            }
#pragma unroll
            for (int j = 0; j < 2; j++) {
                ldsm_x4(bh[j], bh_base + j * (16 * PSTRB) + kk * 32);
                ldsm_x4(bl[j], bl_base + j * (16 * PSTRB) + kk * 32);
            }
#pragma unroll
            for (int nt = 0; nt < 4; nt++) {
                const uint32_t* bhp = &bh[nt >> 1][(nt & 1) * 2];
                const uint32_t* blp = &bl[nt >> 1][(nt & 1) * 2];
#pragma unroll
                for (int mt = 0; mt < 4; mt++) {
                    mma_bf16(acc[mt][nt], afh[mt], bhp);
                    mma_bf16(acc[mt][nt], afh[mt], blp);
                    mma_bf16(acc[mt][nt], afl[mt], bhp);
                }
            }
        }
        __syncthreads();
    }
#pragma unroll
    for (int mt = 0; mt < 4; mt++)
#pragma unroll
        for (int nt = 0; nt < 4; nt++) {
            int r = m0 + wm + mt * 16 + gid;
            int c = n0 + wn + nt * 8 + tig * 2;
            *(float2*)(out + (size_t)r * D_ + c) = make_float2(acc[mt][nt][0], acc[mt][nt][1]);
            *(float2*)(out + (size_t)(r + 8) * D_ + c) = make_float2(acc[mt][nt][2], acc[mt][nt][3]);
        }
}

// ---------------- launch ----------------
extern "C" void kernel_launch(void* const* d_in, const int* in_sizes, int n_in,
                              void* d_out, int out_size) {
    (void)in_sizes; (void)n_in; (void)out_size;
    const float* x   = (const float*)d_in[0];
    const float* qw  = (const float*)d_in[1];
    const float* kw  = (const float*)d_in[2];
    const float* vw  = (const float*)d_in[3];
    const float* wow = (const float*)d_in[4];
    float* out = (float*)d_out;

    const int PROJ_SMEM = 2 * PSTGB;   // 61440
    const int WO_SMEM   = 2 * WSTGB;   // 81920
    cudaFuncSetAttribute(attn_k, cudaFuncAttributeMaxDynamicSharedMemorySize, ATTN_SMEM_B);
    cudaFuncSetAttribute(gemm_proj_k, cudaFuncAttributeMaxDynamicSharedMemorySize, PROJ_SMEM);
    cudaFuncSetAttribute(gemm_wo_k, cudaFuncAttributeMaxDynamicSharedMemorySize, WO_SMEM);

    pack_w_k<<<(NCAT_ * D_ + 255) / 256, 256>>>(qw, kw, vw, wow);
    lif_x_k<<<(BCD_ + 255) / 256, 256>>>(x);
    gemm_proj_k<<<dim3(NCAT_ / 128, M_ / 128), 256, PROJ_SMEM>>>();
    lif_proj8_k<<<(BC_ * (NCAT_ / 4) + 255) / 256, 256>>>();
    transpose_v_k<<<dim3(C_ / 32, MKV_ / 32, T_ * B_), dim3(32, 8)>>>();
    attn_k<<<dim3(C_ / 128, T_ * B_ * H_), 256, ATTN_SMEM_B>>>();
    gemm_wo_k<<<dim3(D_ / 128, M_ / 128), 256, WO_SMEM>>>(out);
}

// round 11
// speedup vs baseline: 1.2087x; 1.2087x over previous
#include <cuda_runtime.h>
#include <cuda_bf16.h>
#include <cstdint>

#define T_ 4
#define B_ 8
#define C_ 512
#define D_ 768
#define H_ 8
#define HD_ 96
#define MKV_ 192
#define NCAT_ 1152            // 768 (q) + 192 (k) + 192 (v)
#define BC_ 4096              // B*C
#define M_ 16384              // T*B*C
#define BCD_ 3145728          // B*C*D

// ---------------- scratch (device globals: no allocation allowed) ----------
__device__ __nv_bfloat16 g_xs[M_ * D_];        // proj_lif spikes (exact 0/1)
__device__ __nv_bfloat16 g_Whi[NCAT_ * D_];    // concat [q_w; k_w; v_w] hi
__device__ __nv_bfloat16 g_Wlo[NCAT_ * D_];    // lo residual
__device__ __nv_bfloat16 g_WOhi[D_ * D_];
__device__ __nv_bfloat16 g_WOlo[D_ * D_];
__device__ float         g_pre[M_ * NCAT_];    // pre-activation of q/k/v proj
__device__ __nv_bfloat16 g_sp[M_ * NCAT_];     // q/k/v spikes (bf16 0/1, exact)
__device__ __nv_bfloat16 g_vT[T_ * B_ * MKV_ * C_]; // v spikes transposed (d-major)
__device__ __nv_bfloat16 g_ahi[M_ * D_];       // attention output hi
__device__ __nv_bfloat16 g_alo[M_ * D_];       // attention output lo

// ---------------- helpers ----------------
__device__ __forceinline__ uint32_t smem_u32(const void* p) {
    uint32_t a;
    asm("{ .reg .u64 t; cvta.to.shared.u64 t, %1; cvt.u32.u64 %0, t; }" : "=r"(a) : "l"(p));
    return a;
}
__device__ __forceinline__ void mma_bf16(float* c, const uint32_t* a, const uint32_t* b) {
    asm volatile(
        "mma.sync.aligned.m16n8k16.row.col.f32.bf16.bf16.f32 "
        "{%0,%1,%2,%3},{%4,%5,%6,%7},{%8,%9},{%0,%1,%2,%3};\n"
        : "+f"(c[0]), "+f"(c[1]), "+f"(c[2]), "+f"(c[3])
        : "r"(a[0]), "r"(a[1]), "r"(a[2]), "r"(a[3]), "r"(b[0]), "r"(b[1]));
}
__device__ __forceinline__ void ldsm_x4(uint32_t* r, uint32_t addr) {
    asm volatile("ldmatrix.sync.aligned.m8n8.x4.shared.b16 {%0,%1,%2,%3}, [%4];"
        : "=r"(r[0]), "=r"(r[1]), "=r"(r[2]), "=r"(r[3]) : "r"(addr));
}
__device__ __forceinline__ void ldsm_x2(uint32_t* r, uint32_t addr) {
    asm volatile("ldmatrix.sync.aligned.m8n8.x2.shared.b16 {%0,%1}, [%2];"
        : "=r"(r[0]), "=r"(r[1]) : "r"(addr));
}
__device__ __forceinline__ void cpa16(uint32_t dst, const void* src) {
    asm volatile("cp.async.ca.shared.global [%0], [%1], 16;" :: "r"(dst), "l"(src));
}
#define CP_COMMIT()  asm volatile("cp.async.commit_group;" ::: "memory")
#define CP_WAIT(n)   asm volatile("cp.async.wait_group %0;" :: "n"(n) : "memory")

// ---------------- kernel 1: split weights into bf16 hi/lo ----------------
__global__ void pack_w_k(const float* __restrict__ qw, const float* __restrict__ kw,
                         const float* __restrict__ vw, const float* __restrict__ wow) {
    int i = blockIdx.x * 256 + threadIdx.x;
    if (i < NCAT_ * D_) {
        int n = i / D_, k = i - n * D_;
        float w;
        if (n < D_)            w = qw[i];
        else if (n < D_ + MKV_) w = kw[(n - D_) * D_ + k];
        else                    w = vw[(n - D_ - MKV_) * D_ + k];
        __nv_bfloat16 hi = __float2bfloat16(w);
        g_Whi[i] = hi;
        g_Wlo[i] = __float2bfloat16(w - __bfloat162float(hi));
    }
    if (i < D_ * D_) {
        float w = wow[i];
        __nv_bfloat16 hi = __float2bfloat16(w);
        g_WOhi[i] = hi;
        g_WOlo[i] = __float2bfloat16(w - __bfloat162float(hi));
    }
}

// ---------------- kernel 2: LIF on x -> xs spikes (bf16 exact) -------------
__global__ void lif_x_k(const float* __restrict__ x) {
    int i = blockIdx.x * 256 + threadIdx.x;
    if (i >= BCD_) return;
    float v = 0.f;
#pragma unroll
    for (int t = 0; t < T_; t++) {
        v = v * 0.5f + x[t * BCD_ + i];
        bool s = (v >= 1.0f);
        g_xs[t * BCD_ + i] = __float2bfloat16(s ? 1.f : 0.f);
        if (s) v = 0.f;
    }
}

// ---------------- kernel 3: projection GEMM  pre = xs @ [Wq;Wk;Wv]^T -------
// r8 (WIN): K-chunk 32, 80B stride, ldmatrix, cp.async.ca double buffer.
#define PSTR 40                 // smem row stride, bf16 units
#define PSTRB 80                // ... bytes
#define PTILE (128 * PSTR)      // tile bf16 units
#define PTILEB (128 * PSTRB)    // tile bytes (10240)
#define PSTGB (3 * PTILEB)      // 30720
#define NCH 24                  // K=768 / 32
__global__ void __launch_bounds__(256)
gemm_proj_k() {
    extern __shared__ __nv_bfloat16 smp[];
    uint32_t sbase = smem_u32(smp);
    int tid = threadIdx.x;
    int lane = tid & 31, warp = tid >> 5;
    int gid = lane >> 2, tig = lane & 3;
    int wm = (warp >> 2) * 64, wn = (warp & 3) * 32;
    int m0 = blockIdx.y * 128, n0 = blockIdx.x * 128;

    uint32_t a_off = (wm + (lane & 15)) * PSTRB + (lane >> 4) * 16;
    uint32_t b_off = (wn + ((lane >> 4) << 3) + (lane & 7)) * PSTRB + ((lane >> 3) & 1) * 16;

    float acc[4][4][4];
#pragma unroll
    for (int a = 0; a < 4; a++)
#pragma unroll
        for (int b = 0; b < 4; b++)
#pragma unroll
            for (int c = 0; c < 4; c++) acc[a][b][c] = 0.f;

    int r0 = tid >> 2, c4b = (tid & 3) * 16;

#pragma unroll
    for (int it = 0; it < 2; it++) {
        int rr = r0 + it * 64;
        cpa16(sbase + rr * PSTRB + c4b,
              (const char*)(g_xs + (size_t)(m0 + rr) * D_) + c4b);
        cpa16(sbase + PTILEB + rr * PSTRB + c4b,
              (const char*)(g_Whi + (size_t)(n0 + rr) * D_) + c4b);
        cpa16(sbase + 2 * PTILEB + rr * PSTRB + c4b,
              (const char*)(g_Wlo + (size_t)(n0 + rr) * D_) + c4b);
    }
    CP_COMMIT();

    for (int c = 0; c < NCH; c++) {
        if (c + 1 < NCH) {
            uint32_t st = ((c + 1) & 1) * PSTGB;
            int kb = (c + 1) * 64;
#pragma unroll
            for (int it = 0; it < 2; it++) {
                int rr = r0 + it * 64;
                cpa16(sbase + st + rr * PSTRB + c4b,
                      (const char*)(g_xs + (size_t)(m0 + rr) * D_) + kb + c4b);
                cpa16(sbase + st + PTILEB + rr * PSTRB + c4b,
                      (const char*)(g_Whi + (size_t)(n0 + rr) * D_) + kb + c4b);
                cpa16(sbase + st + 2 * PTILEB + rr * PSTRB + c4b,
                      (const char*)(g_Wlo + (size_t)(n0 + rr) * D_) + kb + c4b);
            }
            CP_COMMIT();
            CP_WAIT(1);
        } else {
            CP_WAIT(0);
        }
        __syncthreads();
        uint32_t off = (c & 1) * PSTGB;
        uint32_t a_base = sbase + off + a_off;
        uint32_t bh_base = sbase + off + PTILEB + b_off;
        uint32_t bl_base = sbase + off + 2 * PTILEB + b_off;
#pragma unroll
        for (int kk = 0; kk < 2; kk++) {
            uint32_t af[4][4], bh[2][4], bl[2][4];
#pragma unroll
            for (int mt = 0; mt < 4; mt++)
                ldsm_x4(af[mt], a_base + mt * (16 * PSTRB) + kk * 32);
#pragma unroll
            for (int j = 0; j < 2; j++) {
                ldsm_x4(bh[j], bh_base + j * (16 * PSTRB) + kk * 32);
                ldsm_x4(bl[j], bl_base + j * (16 * PSTRB) + kk * 32);
            }
#pragma unroll
            for (int nt = 0; nt < 4; nt++) {
                const uint32_t* bhp = &bh[nt >> 1][(nt & 1) * 2];
                const uint32_t* blp = &bl[nt >> 1][(nt & 1) * 2];
#pragma unroll
                for (int mt = 0; mt < 4; mt++) {
                    mma_bf16(acc[mt][nt], af[mt], bhp);
                    mma_bf16(acc[mt][nt], af[mt], blp);
                }
            }
        }
        __syncthreads();
    }
#pragma unroll
    for (int mt = 0; mt < 4; mt++)
#pragma unroll
        for (int nt = 0; nt < 4; nt++) {
            int r = m0 + wm + mt * 16 + gid;
            int c = n0 + wn + nt * 8 + tig * 2;
            *(float2*)(g_pre + (size_t)r * NCAT_ + c) = make_float2(acc[mt][nt][0], acc[mt][nt][1]);
            *(float2*)(g_pre + (size_t)(r + 8) * NCAT_ + c) = make_float2(acc[mt][nt][2], acc[mt][nt][3]);
        }
}

// ---------------- kernel 4: LIF on projections -> bf16 spikes (coalesced) --
__global__ void lif_proj8_k() {
    int i = blockIdx.x * 256 + threadIdx.x;          // one per (bc, n4)
    if (i >= BC_ * (NCAT_ / 4)) return;
    int bc = i / (NCAT_ / 4), n4 = (i - bc * (NCAT_ / 4)) * 4;
    float v[4] = {0.f, 0.f, 0.f, 0.f};
#pragma unroll
    for (int t = 0; t < T_; t++) {
        size_t row = (size_t)(t * BC_ + bc);
        float4 p = *(const float4*)(g_pre + row * NCAT_ + n4);
        float pv[4] = {p.x, p.y, p.z, p.w};
        uint32_t w[2] = {0u, 0u};
#pragma unroll
        for (int j = 0; j < 4; j++) {
            v[j] = v[j] * 0.5f + pv[j];
            bool sp = (v[j] >= 1.0f);
            if (sp) { w[j >> 1] |= 0x3F80u << ((j & 1) * 16); v[j] = 0.f; }
        }
        *(uint2*)(g_sp + row * NCAT_ + n4) = make_uint2(w[0], w[1]);
    }
}

// ---------------- kernel 5: transpose v spikes (coalesced tiles, bf16) -----
__global__ void transpose_v_k() {
    __shared__ __nv_bfloat16 smT[32][33];
    int c0 = blockIdx.x * 32, n0 = blockIdx.y * 32, z = blockIdx.z; // z = t*B+b
    int t = z >> 3, b = z & 7;
    int tx = threadIdx.x, ty = threadIdx.y;
#pragma unroll
    for (int j = 0; j < 4; j++) {
        int r = ty + j * 8;
        smT[r][tx] = g_sp[(size_t)(t * BC_ + b * C_ + c0 + r) * NCAT_ + (D_ + MKV_) + n0 + tx];
    }
    __syncthreads();
#pragma unroll
    for (int j = 0; j < 4; j++) {
        int nv = ty + j * 8;
        g_vT[((size_t)z * MKV_ + n0 + nv) * C_ + c0 + tx] = smT[tx][nv];
    }
}

// ---------------- kernel 6: bf16 attention, 64-row Q blocks, 2 CTAs/SM -----
// smem bytes: Q[64x208]=13312 | K[128x208]=26624 | V[96x272]=26112 |
//             S[64x272]=17408   total 83456 -> 2 CTAs/SM
#define AQB 13312
#define AKB 26624
#define AVB 26112
#define AOK AQB
#define AOV (AQB + AKB)
#define AOS (AQB + AKB + AVB)
#define ATTN_SMEM_B (AOS + 17408)
__global__ void __launch_bounds__(256)
attn_k() {
    extern __shared__ char smA[];
    uint32_t sb = smem_u32(smA);
    __nv_bfloat16* sS = (__nv_bfloat16*)(smA + AOS);

    int tid = threadIdx.x, lane = tid & 31, warp = tid >> 5;
    int gid = lane >> 2, tig = lane & 3;
    int wm = (warp >> 2) * 32;   // 2 m-groups of 32 rows
    int wn1 = (warp & 3) * 32;   // key cols in mma1
    int wn2 = (warp & 3) * 24;   // d cols in mma2
    int qb = blockIdx.x;         // q row block (0..7), 64 rows each
    int tbh = blockIdx.y;        // (t*B+b)*H + h
    int h = tbh & 7, tb = tbh >> 3;
    int kvh = h >> 2;
    int qcol = h * HD_;
    int kcol = D_ + kvh * HD_;
    int rowbase = tb * C_;

    // ldmatrix lane-address bases
    uint32_t q_base = sb + (wm + (lane & 15)) * 208 + (lane >> 4) * 16;
    uint32_t k_base = sb + AOK + (wn1 + ((lane >> 4) << 3) + (lane & 7)) * 208
                      + ((lane >> 3) & 1) * 16;
    uint32_t s_base = sb + AOS + (wm + (lane & 15)) * 272 + (lane >> 4) * 16;
    uint32_t v_base4 = sb + AOV + (wn2 + ((lane >> 4) << 3) + (lane & 7)) * 272
                       + ((lane >> 3) & 1) * 16;
    uint32_t v_base2 = sb + AOV + (wn2 + 16 + (lane & 7)) * 272 + ((lane >> 3) & 1) * 16;

    // Q tile: 64 rows x 96 cols = 768 x 16B chunks
#pragma unroll
    for (int it = 0; it < 3; it++) {
        int idx = tid + it * 256;
        int r = idx / 12, c = idx % 12;
        cpa16(sb + r * 208 + c * 16,
              (const char*)(g_sp + (size_t)(rowbase + qb * 64 + r) * NCAT_ + qcol) + c * 16);
    }
    CP_COMMIT();

    float acc2[2][3][4];
#pragma unroll
    for (int a = 0; a < 2; a++)
#pragma unroll
        for (int b = 0; b < 3; b++)
#pragma unroll
            for (int c = 0; c < 4; c++) acc2[a][b][c] = 0.f;

    for (int kc = 0; kc < 4; kc++) {
        // load K chunk (128 keys x 96) and V^T chunk (96 d x 128 keys)
#pragma unroll
        for (int it = 0; it < 6; it++) {
            int idx = tid + it * 256;
            int r = idx / 12, c = idx % 12;
            cpa16(sb + AOK + r * 208 + c * 16,
                  (const char*)(g_sp + (size_t)(rowbase + kc * 128 + r) * NCAT_ + kcol) + c * 16);
        }
#pragma unroll
        for (int it = 0; it < 6; it++) {
            int idx = tid + it * 256;
            int r = idx >> 4, c = idx & 15;
            cpa16(sb + AOV + r * 272 + c * 16,
                  (const char*)(g_vT + (size_t)(tb * MKV_ + kvh * HD_ + r) * C_ + kc * 128) + c * 16);
        }
        CP_COMMIT();
        CP_WAIT(0);
        __syncthreads();

        // mma1: counts = q @ k^T   (64 x 128, K=96) — exact integers
        float acc1[2][4][4];
#pragma unroll
        for (int a = 0; a < 2; a++)
#pragma unroll
            for (int b = 0; b < 4; b++)
#pragma unroll
                for (int c = 0; c < 4; c++) acc1[a][b][c] = 0.f;
#pragma unroll
        for (int kk = 0; kk < 6; kk++) {
            uint32_t af[2][4], bk[2][4];
#pragma unroll
            for (int mt = 0; mt < 2; mt++)
                ldsm_x4(af[mt], q_base + mt * (16 * 208) + kk * 32);
#pragma unroll
            for (int j = 0; j < 2; j++)
                ldsm_x4(bk[j], k_base + j * (16 * 208) + kk * 32);
#pragma unroll
            for (int nt = 0; nt < 4; nt++) {
                const uint32_t* bb = &bk[nt >> 1][(nt & 1) * 2];
#pragma unroll
                for (int mt = 0; mt < 2; mt++) mma_bf16(acc1[mt][nt], af[mt], bb);
            }
        }
        // store counts to smem as bf16 (exact: <=96)
#pragma unroll
        for (int mt = 0; mt < 2; mt++)
#pragma unroll
            for (int nt = 0; nt < 4; nt++) {
                int r = wm + mt * 16 + gid;
                int cc = wn1 + nt * 8 + tig * 2;
                __nv_bfloat162 p0, p1;
                p0.x = __float2bfloat16(acc1[mt][nt][0]);
                p0.y = __float2bfloat16(acc1[mt][nt][1]);
                p1.x = __float2bfloat16(acc1[mt][nt][2]);
                p1.y = __float2bfloat16(acc1[mt][nt][3]);
                *(__nv_bfloat162*)(sS + r * 136 + cc) = p0;
                *(__nv_bfloat162*)(sS + (r + 8) * 136 + cc) = p1;
            }
        __syncthreads();

        // mma2: acc2 += counts @ v   (64 x 96, K=128) — exact integers
#pragma unroll
        for (int kk = 0; kk < 8; kk++) {
            uint32_t af[2][4], bv[6];
#pragma unroll
            for (int mt = 0; mt < 2; mt++)
                ldsm_x4(af[mt], s_base + mt * (16 * 272) + kk * 32);
            ldsm_x4(bv, v_base4 + kk * 32);          // nt0, nt1
            ldsm_x2(bv + 4, v_base2 + kk * 32);      // nt2
#pragma unroll
            for (int nt = 0; nt < 3; nt++) {
                const uint32_t* bb = &bv[nt * 2];
#pragma unroll
                for (int mt = 0; mt < 2; mt++) mma_bf16(acc2[mt][nt], af[mt], bb);
            }
        }
        __syncthreads();
    }

    // epilogue: scale by 0.1, hi/lo split for the wo GEMM
#pragma unroll
    for (int mt = 0; mt < 2; mt++)
#pragma unroll
        for (int nt = 0; nt < 3; nt++) {
            int r = rowbase + qb * 64 + wm + mt * 16 + gid;
            int cb = qcol + wn2 + nt * 8 + tig * 2;
#pragma unroll
            for (int half = 0; half < 2; half++) {
                int rr = r + half * 8;
                float v0 = 0.1f * acc2[mt][nt][half * 2 + 0];
                float v1 = 0.1f * acc2[mt][nt][half * 2 + 1];
                __nv_bfloat162 hi2, lo2;
                hi2.x = __float2bfloat16(v0);
                hi2.y = __float2bfloat16(v1);
                lo2.x = __float2bfloat16(v0 - __bfloat162float(hi2.x));
                lo2.y = __float2bfloat16(v1 - __bfloat162float(hi2.y));
                *(__nv_bfloat162*)(g_ahi + (size_t)rr * D_ + cb) = hi2;
                *(__nv_bfloat162*)(g_alo + (size_t)rr * D_ + cb) = lo2;
            }
        }
}

// ---------------- kernel 7: output GEMM  d_out = attn @ wo^T ----------------
// r8 (WIN): cp.async.ca double buffer; A/B hi/lo -> 3 MMAs per k-step.
#define WSTGB (4 * PTILEB)     // 40960
__global__ void __launch_bounds__(256)
gemm_wo_k(float* __restrict__ out) {
    extern __shared__ __nv_bfloat16 smw[];
    uint32_t sbase = smem_u32(smw);
    int tid = threadIdx.x;
    int lane = tid & 31, warp = tid >> 5;
    int gid = lane >> 2, tig = lane & 3;
    int wm = (warp >> 2) * 64, wn = (warp & 3) * 32;
    int m0 = blockIdx.y * 128, n0 = blockIdx.x * 128;

    uint32_t a_off = (wm + (lane & 15)) * PSTRB + (lane >> 4) * 16;
    uint32_t b_off = (wn + ((lane >> 4) << 3) + (lane & 7)) * PSTRB + ((lane >> 3) & 1) * 16;

    float acc[4][4][4];
#pragma unroll
    for (int a = 0; a < 4; a++)
#pragma unroll
        for (int b = 0; b < 4; b++)
#pragma unroll
            for (int c = 0; c < 4; c++) acc[a][b][c] = 0.f;

    int r0 = tid >> 2, c4b = (tid & 3) * 16;

#pragma unroll
    for (int it = 0; it < 2; it++) {
        int rr = r0 + it * 64;
        cpa16(sbase + rr * PSTRB + c4b,
              (const char*)(g_ahi + (size_t)(m0 + rr) * D_) + c4b);
        cpa16(sbase + PTILEB + rr * PSTRB + c4b,
              (const char*)(g_alo + (size_t)(m0 + rr) * D_) + c4b);
        cpa16(sbase + 2 * PTILEB + rr * PSTRB + c4b,
              (const char*)(g_WOhi + (size_t)(n0 + rr) * D_) + c4b);
        cpa16(sbase + 3 * PTILEB + rr * PSTRB + c4b,
              (const char*)(g_WOlo + (size_t)(n0 + rr) * D_) + c4b);
    }
    CP_COMMIT();

    for (int c = 0; c < NCH; c++) {
        if (c + 1 < NCH) {
            uint32_t st = ((c + 1) & 1) * WSTGB;
            int kb = (c + 1) * 64;
#pragma unroll
            for (int it = 0; it < 2; it++) {
                int rr = r0 + it * 64;
                cpa16(sbase + st + rr * PSTRB + c4b,
                      (const char*)(g_ahi + (size_t)(m0 + rr) * D_) + kb + c4b);
                cpa16(sbase + st + PTILEB + rr * PSTRB + c4b,
                      (const char*)(g_alo + (size_t)(m0 + rr) * D_) + kb + c4b);
                cpa16(sbase + st + 2 * PTILEB + rr * PSTRB + c4b,
                      (const char*)(g_WOhi + (size_t)(n0 + rr) * D_) + kb + c4b);
                cpa16(sbase + st + 3 * PTILEB + rr * PSTRB + c4b,
                      (const char*)(g_WOlo + (size_t)(n0 + rr) * D_) + kb + c4b);
            }
            CP_COMMIT();
            CP_WAIT(1);
        } else {
            CP_WAIT(0);
        }
        __syncthreads();
        uint32_t off = (c & 1) * WSTGB;
        uint32_t ah_base = sbase + off + a_off;
        uint32_t al_base = sbase + off + PTILEB + a_off;
        uint32_t bh_base = sbase + off + 2 * PTILEB + b_off;
        uint32_t bl_base = sbase + off + 3 * PTILEB + b_off;
#pragma unroll
        for (int kk = 0; kk < 2; kk++) {
            uint32_t afh[4][4], afl[4][4], bh[2][4], bl[2][4];
#pragma unroll
            for (int mt = 0; mt < 4; mt++) {
                ldsm_x4(afh[mt], ah_base + mt * (16 * PSTRB) + kk * 32);
                ldsm_x4(afl[mt], al_base + mt * (16 * PSTRB) + kk * 32);
            }
#pragma unroll
            for (int j = 0; j < 2; j++) {
                ldsm_x4(bh[j], bh_base + j * (16 * PSTRB) + kk * 32);
                ldsm_x4(bl[j], bl_base + j * (16 * PSTRB) + kk * 32);
            }
#pragma unroll
            for (int nt = 0; nt < 4; nt++) {
                const uint32_t* bhp = &bh[nt >> 1][(nt & 1) * 2];
                const uint32_t* blp = &bl[nt >> 1][(nt & 1) * 2];
#pragma unroll
                for (int mt = 0; mt < 4; mt++) {
                    mma_bf16(acc[mt][nt], afh[mt], bhp);
                    mma_bf16(acc[mt][nt], afh[mt], blp);
                    mma_bf16(acc[mt][nt], afl[mt], bhp);
                }
            }
        }
        __syncthreads();
    }
#pragma unroll
    for (int mt = 0; mt < 4; mt++)
#pragma unroll
        for (int nt = 0; nt < 4; nt++) {
            int r = m0 + wm + mt * 16 + gid;
            int c = n0 + wn + nt * 8 + tig * 2;
            *(float2*)(out + (size_t)r * D_ + c) = make_float2(acc[mt][nt][0], acc[mt][nt][1]);
            *(float2*)(out + (size_t)(r + 8) * D_ + c) = make_float2(acc[mt][nt][2], acc[mt][nt][3]);
        }
}

// ---------------- launch ----------------
extern "C" void kernel_launch(void* const* d_in, const int* in_sizes, int n_in,
                              void* d_out, int out_size) {
    (void)in_sizes; (void)n_in; (void)out_size;
    const float* x   = (const float*)d_in[0];
    const float* qw  = (const float*)d_in[1];
    const float* kw  = (const float*)d_in[2];
    const float* vw  = (const float*)d_in[3];
    const float* wow = (const float*)d_in[4];
    float* out = (float*)d_out;

    const int PROJ_SMEM = 2 * PSTGB;   // 61440
    const int WO_SMEM   = 2 * WSTGB;   // 81920
    cudaFuncSetAttribute(attn_k, cudaFuncAttributeMaxDynamicSharedMemorySize, ATTN_SMEM_B);
    cudaFuncSetAttribute(gemm_proj_k, cudaFuncAttributeMaxDynamicSharedMemorySize, PROJ_SMEM);
    cudaFuncSetAttribute(gemm_wo_k, cudaFuncAttributeMaxDynamicSharedMemorySize, WO_SMEM);

    pack_w_k<<<(NCAT_ * D_ + 255) / 256, 256>>>(qw, kw, vw, wow);
    lif_x_k<<<(BCD_ + 255) / 256, 256>>>(x);
    gemm_proj_k<<<dim3(NCAT_ / 128, M_ / 128), 256, PROJ_SMEM>>>();
    lif_proj8_k<<<(BC_ * (NCAT_ / 4) + 255) / 256, 256>>>();
    transpose_v_k<<<dim3(C_ / 32, MKV_ / 32, T_ * B_), dim3(32, 8)>>>();
    attn_k<<<dim3(C_ / 64, T_ * B_ * H_), 256, ATTN_SMEM_B>>>();
    gemm_wo_k<<<dim3(D_ / 128, M_ / 128), 256, WO_SMEM>>>(out);
}

// round 12
// speedup vs baseline: 1.2255x; 1.0139x over previous
#include <cuda_runtime.h>
#include <cuda_bf16.h>
#include <cstdint>

#define T_ 4
#define B_ 8
#define C_ 512
#define D_ 768
#define H_ 8
#define HD_ 96
#define MKV_ 192
#define NCAT_ 1152            // 768 (q) + 192 (k) + 192 (v)
#define BC_ 4096              // B*C
#define M_ 16384              // T*B*C
#define BCD_ 3145728          // B*C*D

// ---------------- scratch (device globals: no allocation allowed) ----------
__device__ __nv_bfloat16 g_xs[M_ * D_];        // proj_lif spikes (exact 0/1)
__device__ __nv_bfloat16 g_Whi[NCAT_ * D_];    // concat [q_w; k_w; v_w] hi
__device__ __nv_bfloat16 g_Wlo[NCAT_ * D_];    // lo residual
__device__ __nv_bfloat16 g_WOhi[D_ * D_];
__device__ __nv_bfloat16 g_WOlo[D_ * D_];
__device__ float         g_pre[M_ * NCAT_];    // pre-activation of q/k/v proj
__device__ __nv_bfloat16 g_sp[M_ * NCAT_];     // q/k/v spikes (bf16 0/1, exact)
__device__ __nv_bfloat16 g_ahi[M_ * D_];       // attention output hi
__device__ __nv_bfloat16 g_alo[M_ * D_];       // attention output lo

// ---------------- helpers ----------------
__device__ __forceinline__ uint32_t smem_u32(const void* p) {
    uint32_t a;
    asm("{ .reg .u64 t; cvta.to.shared.u64 t, %1; cvt.u32.u64 %0, t; }" : "=r"(a) : "l"(p));
    return a;
}
__device__ __forceinline__ void mma_bf16(float* c, const uint32_t* a, const uint32_t* b) {
    asm volatile(
        "mma.sync.aligned.m16n8k16.row.col.f32.bf16.bf16.f32 "
        "{%0,%1,%2,%3},{%4,%5,%6,%7},{%8,%9},{%0,%1,%2,%3};\n"
        : "+f"(c[0]), "+f"(c[1]), "+f"(c[2]), "+f"(c[3])
        : "r"(a[0]), "r"(a[1]), "r"(a[2]), "r"(a[3]), "r"(b[0]), "r"(b[1]));
}
__device__ __forceinline__ void ldsm_x4(uint32_t* r, uint32_t addr) {
    asm volatile("ldmatrix.sync.aligned.m8n8.x4.shared.b16 {%0,%1,%2,%3}, [%4];"
        : "=r"(r[0]), "=r"(r[1]), "=r"(r[2]), "=r"(r[3]) : "r"(addr));
}
__device__ __forceinline__ void ldsm_x4_t(uint32_t* r, uint32_t addr) {
    asm volatile("ldmatrix.sync.aligned.m8n8.x4.trans.shared.b16 {%0,%1,%2,%3}, [%4];"
        : "=r"(r[0]), "=r"(r[1]), "=r"(r[2]), "=r"(r[3]) : "r"(addr));
}
__device__ __forceinline__ void ldsm_x2_t(uint32_t* r, uint32_t addr) {
    asm volatile("ldmatrix.sync.aligned.m8n8.x2.trans.shared.b16 {%0,%1}, [%2];"
        : "=r"(r[0]), "=r"(r[1]) : "r"(addr));
}
__device__ __forceinline__ void cpa16(uint32_t dst, const void* src) {
    asm volatile("cp.async.ca.shared.global [%0], [%1], 16;" :: "r"(dst), "l"(src));
}
#define CP_COMMIT()  asm volatile("cp.async.commit_group;" ::: "memory")
#define CP_WAIT(n)   asm volatile("cp.async.wait_group %0;" :: "n"(n) : "memory")

// ---------------- kernel 1: split weights into bf16 hi/lo ----------------
__global__ void pack_w_k(const float* __restrict__ qw, const float* __restrict__ kw,
                         const float* __restrict__ vw, const float* __restrict__ wow) {
    int i = blockIdx.x * 256 + threadIdx.x;
    if (i < NCAT_ * D_) {
        int n = i / D_, k = i - n * D_;
        float w;
        if (n < D_)            w = qw[i];
        else if (n < D_ + MKV_) w = kw[(n - D_) * D_ + k];
        else                    w = vw[(n - D_ - MKV_) * D_ + k];
        __nv_bfloat16 hi = __float2bfloat16(w);
        g_Whi[i] = hi;
        g_Wlo[i] = __float2bfloat16(w - __bfloat162float(hi));
    }
    if (i < D_ * D_) {
        float w = wow[i];
        __nv_bfloat16 hi = __float2bfloat16(w);
        g_WOhi[i] = hi;
        g_WOlo[i] = __float2bfloat16(w - __bfloat162float(hi));
    }
}

// ---------------- kernel 2: LIF on x -> xs spikes (bf16 exact) -------------
__global__ void lif_x_k(const float* __restrict__ x) {
    int i = blockIdx.x * 256 + threadIdx.x;
    if (i >= BCD_) return;
    float v = 0.f;
#pragma unroll
    for (int t = 0; t < T_; t++) {
        v = v * 0.5f + x[t * BCD_ + i];
        bool s = (v >= 1.0f);
        g_xs[t * BCD_ + i] = __float2bfloat16(s ? 1.f : 0.f);
        if (s) v = 0.f;
    }
}

// ---------------- kernel 3: projection GEMM  pre = xs @ [Wq;Wk;Wv]^T -------
// r8 (WIN): K-chunk 32, 80B stride, ldmatrix, cp.async.ca double buffer.
#define PSTR 40                 // smem row stride, bf16 units
#define PSTRB 80                // ... bytes
#define PTILE (128 * PSTR)      // tile bf16 units
#define PTILEB (128 * PSTRB)    // tile bytes (10240)
#define PSTGB (3 * PTILEB)      // 30720
#define NCH 24                  // K=768 / 32
__global__ void __launch_bounds__(256)
gemm_proj_k() {
    extern __shared__ __nv_bfloat16 smp[];
    uint32_t sbase = smem_u32(smp);
    int tid = threadIdx.x;
    int lane = tid & 31, warp = tid >> 5;
    int gid = lane >> 2, tig = lane & 3;
    int wm = (warp >> 2) * 64, wn = (warp & 3) * 32;
    int m0 = blockIdx.y * 128, n0 = blockIdx.x * 128;

    uint32_t a_off = (wm + (lane & 15)) * PSTRB + (lane >> 4) * 16;
    uint32_t b_off = (wn + ((lane >> 4) << 3) + (lane & 7)) * PSTRB + ((lane >> 3) & 1) * 16;

    float acc[4][4][4];
#pragma unroll
    for (int a = 0; a < 4; a++)
#pragma unroll
        for (int b = 0; b < 4; b++)
#pragma unroll
            for (int c = 0; c < 4; c++) acc[a][b][c] = 0.f;

    int r0 = tid >> 2, c4b = (tid & 3) * 16;

#pragma unroll
    for (int it = 0; it < 2; it++) {
        int rr = r0 + it * 64;
        cpa16(sbase + rr * PSTRB + c4b,
              (const char*)(g_xs + (size_t)(m0 + rr) * D_) + c4b);
        cpa16(sbase + PTILEB + rr * PSTRB + c4b,
              (const char*)(g_Whi + (size_t)(n0 + rr) * D_) + c4b);
        cpa16(sbase + 2 * PTILEB + rr * PSTRB + c4b,
              (const char*)(g_Wlo + (size_t)(n0 + rr) * D_) + c4b);
    }
    CP_COMMIT();

    for (int c = 0; c < NCH; c++) {
        if (c + 1 < NCH) {
            uint32_t st = ((c + 1) & 1) * PSTGB;
            int kb = (c + 1) * 64;
#pragma unroll
            for (int it = 0; it < 2; it++) {
                int rr = r0 + it * 64;
                cpa16(sbase + st + rr * PSTRB + c4b,
                      (const char*)(g_xs + (size_t)(m0 + rr) * D_) + kb + c4b);
                cpa16(sbase + st + PTILEB + rr * PSTRB + c4b,
                      (const char*)(g_Whi + (size_t)(n0 + rr) * D_) + kb + c4b);
                cpa16(sbase + st + 2 * PTILEB + rr * PSTRB + c4b,
                      (const char*)(g_Wlo + (size_t)(n0 + rr) * D_) + kb + c4b);
            }
            CP_COMMIT();
            CP_WAIT(1);
        } else {
            CP_WAIT(0);
        }
        __syncthreads();
        uint32_t off = (c & 1) * PSTGB;
        uint32_t a_base = sbase + off + a_off;
        uint32_t bh_base = sbase + off + PTILEB + b_off;
        uint32_t bl_base = sbase + off + 2 * PTILEB + b_off;
#pragma unroll
        for (int kk = 0; kk < 2; kk++) {
            uint32_t af[4][4], bh[2][4], bl[2][4];
#pragma unroll
            for (int mt = 0; mt < 4; mt++)
                ldsm_x4(af[mt], a_base + mt * (16 * PSTRB) + kk * 32);
#pragma unroll
            for (int j = 0; j < 2; j++) {
                ldsm_x4(bh[j], bh_base + j * (16 * PSTRB) + kk * 32);
                ldsm_x4(bl[j], bl_base + j * (16 * PSTRB) + kk * 32);
            }
#pragma unroll
            for (int nt = 0; nt < 4; nt++) {
                const uint32_t* bhp = &bh[nt >> 1][(nt & 1) * 2];
                const uint32_t* blp = &bl[nt >> 1][(nt & 1) * 2];
#pragma unroll
                for (int mt = 0; mt < 4; mt++) {
                    mma_bf16(acc[mt][nt], af[mt], bhp);
                    mma_bf16(acc[mt][nt], af[mt], blp);
                }
            }
        }
        __syncthreads();
    }
#pragma unroll
    for (int mt = 0; mt < 4; mt++)
#pragma unroll
        for (int nt = 0; nt < 4; nt++) {
            int r = m0 + wm + mt * 16 + gid;
            int c = n0 + wn + nt * 8 + tig * 2;
            *(float2*)(g_pre + (size_t)r * NCAT_ + c) = make_float2(acc[mt][nt][0], acc[mt][nt][1]);
            *(float2*)(g_pre + (size_t)(r + 8) * NCAT_ + c) = make_float2(acc[mt][nt][2], acc[mt][nt][3]);
        }
}

// ---------------- kernel 4: LIF on projections -> bf16 spikes (coalesced) --
__global__ void lif_proj8_k() {
    int i = blockIdx.x * 256 + threadIdx.x;          // one per (bc, n4)
    if (i >= BC_ * (NCAT_ / 4)) return;
    int bc = i / (NCAT_ / 4), n4 = (i - bc * (NCAT_ / 4)) * 4;
    float v[4] = {0.f, 0.f, 0.f, 0.f};
#pragma unroll
    for (int t = 0; t < T_; t++) {
        size_t row = (size_t)(t * BC_ + bc);
        float4 p = *(const float4*)(g_pre + row * NCAT_ + n4);
        float pv[4] = {p.x, p.y, p.z, p.w};
        uint32_t w[2] = {0u, 0u};
#pragma unroll
        for (int j = 0; j < 4; j++) {
            v[j] = v[j] * 0.5f + pv[j];
            bool sp = (v[j] >= 1.0f);
            if (sp) { w[j >> 1] |= 0x3F80u << ((j & 1) * 16); v[j] = 0.f; }
        }
        *(uint2*)(g_sp + row * NCAT_ + n4) = make_uint2(w[0], w[1]);
    }
}

// ---------------- kernel 5: bf16 attention, V via ldmatrix.trans -----------
// No g_vT / transpose kernel: V tiles loaded key-major (same loader as K),
// mma2 B-fragments come from ldsm.trans. Values identical to round 9.
// smem bytes: Q[128x208]=26624 | K0,K1[128x208] | V0,V1[128x208] | S[128x272]
#define AOK0 26624
#define AOV0 (26624 * 3)           // 79872
#define AOS  (26624 * 5)           // 133120
#define ATTN_SMEM_B (AOS + 34816)  // 167936
__global__ void __launch_bounds__(256)
attn_k() {
    extern __shared__ char smA[];
    uint32_t sb = smem_u32(smA);
    __nv_bfloat16* sS = (__nv_bfloat16*)(smA + AOS);

    int tid = threadIdx.x, lane = tid & 31, warp = tid >> 5;
    int gid = lane >> 2, tig = lane & 3;
    int wm = (warp >> 2) * 64;
    int wn1 = (warp & 3) * 32;  // key cols in mma1
    int wn2 = (warp & 3) * 24;  // d cols in mma2
    int qb = blockIdx.x;        // q row block (0..3)
    int tbh = blockIdx.y;       // (t*B+b)*H + h
    int h = tbh & 7, tb = tbh >> 3;
    int kvh = h >> 2;
    int qcol = h * HD_;
    int kcol = D_ + kvh * HD_;
    int vcol = D_ + MKV_ + kvh * HD_;
    int rowbase = tb * C_;

    // ldmatrix lane-address offsets
    uint32_t q_base = sb + (wm + (lane & 15)) * 208 + (lane >> 4) * 16;
    uint32_t k_off = (wn1 + ((lane >> 4) << 3) + (lane & 7)) * 208 + ((lane >> 3) & 1) * 16;
    uint32_t s_base = sb + AOS + (wm + (lane & 15)) * 272 + (lane >> 4) * 16;
    // trans-ldsm V: lane -> key row (lane&15), col group (lane>>4)*8 within wn2
    uint32_t v4_off = (lane & 15) * 208 + wn2 * 2 + (lane >> 4) * 16;
    uint32_t v2_off = (lane & 15) * 208 + (wn2 + 16) * 2;
    uint32_t k_stage[2] = { sb + AOK0 + k_off, sb + AOK0 + 26624 + k_off };
    uint32_t v4_stage[2] = { sb + AOV0 + v4_off, sb + AOV0 + 26624 + v4_off };
    uint32_t v2_stage[2] = { sb + AOV0 + v2_off, sb + AOV0 + 26624 + v2_off };

    // prologue: Q + K(kc=0) + V(kc=0), one commit group
#pragma unroll
    for (int it = 0; it < 6; it++) {
        int idx = tid + it * 256;
        int r = idx / 12, c = idx % 12;
        cpa16(sb + r * 208 + c * 16,
              (const char*)(g_sp + (size_t)(rowbase + qb * 128 + r) * NCAT_ + qcol) + c * 16);
    }
#pragma unroll
    for (int it = 0; it < 6; it++) {
        int idx = tid + it * 256;
        int r = idx / 12, c = idx % 12;
        cpa16(sb + AOK0 + r * 208 + c * 16,
              (const char*)(g_sp + (size_t)(rowbase + r) * NCAT_ + kcol) + c * 16);
    }
#pragma unroll
    for (int it = 0; it < 6; it++) {
        int idx = tid + it * 256;
        int r = idx / 12, c = idx % 12;
        cpa16(sb + AOV0 + r * 208 + c * 16,
              (const char*)(g_sp + (size_t)(rowbase + r) * NCAT_ + vcol) + c * 16);
    }
    CP_COMMIT();

    float acc2[4][3][4];
#pragma unroll
    for (int a = 0; a < 4; a++)
#pragma unroll
        for (int b = 0; b < 3; b++)
#pragma unroll
            for (int c = 0; c < 4; c++) acc2[a][b][c] = 0.f;

    for (int kc = 0; kc < 4; kc++) {
        if (kc + 1 < 4) {
            uint32_t kst = sb + AOK0 + ((kc + 1) & 1) * 26624;
            uint32_t vst = sb + AOV0 + ((kc + 1) & 1) * 26624;
#pragma unroll
            for (int it = 0; it < 6; it++) {
                int idx = tid + it * 256;
                int r = idx / 12, c = idx % 12;
                cpa16(kst + r * 208 + c * 16,
                      (const char*)(g_sp + (size_t)(rowbase + (kc + 1) * 128 + r) * NCAT_ + kcol) + c * 16);
            }
#pragma unroll
            for (int it = 0; it < 6; it++) {
                int idx = tid + it * 256;
                int r = idx / 12, c = idx % 12;
                cpa16(vst + r * 208 + c * 16,
                      (const char*)(g_sp + (size_t)(rowbase + (kc + 1) * 128 + r) * NCAT_ + vcol) + c * 16);
            }
            CP_COMMIT();
            CP_WAIT(1);
        } else {
            CP_WAIT(0);
        }
        __syncthreads();
        int st = kc & 1;

        // mma1: counts = q @ k^T   (128 x 128, K=96) — exact integers
        float acc1[4][4][4];
#pragma unroll
        for (int a = 0; a < 4; a++)
#pragma unroll
            for (int b = 0; b < 4; b++)
#pragma unroll
                for (int c = 0; c < 4; c++) acc1[a][b][c] = 0.f;
#pragma unroll
        for (int kk = 0; kk < 6; kk++) {
            uint32_t af[4][4], bk[2][4];
#pragma unroll
            for (int mt = 0; mt < 4; mt++)
                ldsm_x4(af[mt], q_base + mt * (16 * 208) + kk * 32);
#pragma unroll
            for (int j = 0; j < 2; j++)
                ldsm_x4(bk[j], k_stage[st] + j * (16 * 208) + kk * 32);
#pragma unroll
            for (int nt = 0; nt < 4; nt++) {
                const uint32_t* bb = &bk[nt >> 1][(nt & 1) * 2];
#pragma unroll
                for (int mt = 0; mt < 4; mt++) mma_bf16(acc1[mt][nt], af[mt], bb);
            }
        }
        // store counts to smem as bf16 (exact: <=96)
#pragma unroll
        for (int mt = 0; mt < 4; mt++)
#pragma unroll
            for (int nt = 0; nt < 4; nt++) {
                int r = wm + mt * 16 + gid;
                int cc = wn1 + nt * 8 + tig * 2;
                __nv_bfloat162 p0, p1;
                p0.x = __float2bfloat16(acc1[mt][nt][0]);
                p0.y = __float2bfloat16(acc1[mt][nt][1]);
                p1.x = __float2bfloat16(acc1[mt][nt][2]);
                p1.y = __float2bfloat16(acc1[mt][nt][3]);
                *(__nv_bfloat162*)(sS + r * 136 + cc) = p0;
                *(__nv_bfloat162*)(sS + (r + 8) * 136 + cc) = p1;
            }
        __syncthreads();

        // mma2: acc2 += counts @ v   (128 x 96, K=128) — exact integers
        // B-fragments from key-major V tile via ldmatrix.trans
#pragma unroll
        for (int kk = 0; kk < 8; kk++) {
            uint32_t af[4][4], bv[6];
#pragma unroll
            for (int mt = 0; mt < 4; mt++)
                ldsm_x4(af[mt], s_base + mt * (16 * 272) + kk * 32);
            ldsm_x4_t(bv, v4_stage[st] + kk * (16 * 208));      // nt0, nt1
            ldsm_x2_t(bv + 4, v2_stage[st] + kk * (16 * 208));  // nt2
#pragma unroll
            for (int nt = 0; nt < 3; nt++) {
                const uint32_t* bb = &bv[nt * 2];
#pragma unroll
                for (int mt = 0; mt < 4; mt++) mma_bf16(acc2[mt][nt], af[mt], bb);
            }
        }
        __syncthreads();
    }

    // epilogue: scale by 0.1, hi/lo split for the wo GEMM
#pragma unroll
    for (int mt = 0; mt < 4; mt++)
#pragma unroll
        for (int nt = 0; nt < 3; nt++) {
            int r = rowbase + qb * 128 + wm + mt * 16 + gid;
            int cb = qcol + wn2 + nt * 8 + tig * 2;
#pragma unroll
            for (int half = 0; half < 2; half++) {
                int rr = r + half * 8;
                float v0 = 0.1f * acc2[mt][nt][half * 2 + 0];
                float v1 = 0.1f * acc2[mt][nt][half * 2 + 1];
                __nv_bfloat162 hi2, lo2;
                hi2.x = __float2bfloat16(v0);
                hi2.y = __float2bfloat16(v1);
                lo2.x = __float2bfloat16(v0 - __bfloat162float(hi2.x));
                lo2.y = __float2bfloat16(v1 - __bfloat162float(hi2.y));
                *(__nv_bfloat162*)(g_ahi + (size_t)rr * D_ + cb) = hi2;
                *(__nv_bfloat162*)(g_alo + (size_t)rr * D_ + cb) = lo2;
            }
        }
}

// ---------------- kernel 6: output GEMM  d_out = attn @ wo^T ----------------
// r8 (WIN): cp.async.ca double buffer; A/B hi/lo -> 3 MMAs per k-step.
#define WSTGB (4 * PTILEB)     // 40960
__global__ void __launch_bounds__(256)
gemm_wo_k(float* __restrict__ out) {
    extern __shared__ __nv_bfloat16 smw[];
    uint32_t sbase = smem_u32(smw);
    int tid = threadIdx.x;
    int lane = tid & 31, warp = tid >> 5;
    int gid = lane >> 2, tig = lane & 3;
    int wm = (warp >> 2) * 64, wn = (warp & 3) * 32;
    int m0 = blockIdx.y * 128, n0 = blockIdx.x * 128;

    uint32_t a_off = (wm + (lane & 15)) * PSTRB + (lane >> 4) * 16;
    uint32_t b_off = (wn + ((lane >> 4) << 3) + (lane & 7)) * PSTRB + ((lane >> 3) & 1) * 16;

    float acc[4][4][4];
#pragma unroll
    for (int a = 0; a < 4; a++)
#pragma unroll
        for (int b = 0; b < 4; b++)
#pragma unroll
            for (int c = 0; c < 4; c++) acc[a][b][c] = 0.f;

    int r0 = tid >> 2, c4b = (tid & 3) * 16;

#pragma unroll
    for (int it = 0; it < 2; it++) {
        int rr = r0 + it * 64;
        cpa16(sbase + rr * PSTRB + c4b,
              (const char*)(g_ahi + (size_t)(m0 + rr) * D_) + c4b);
        cpa16(sbase + PTILEB + rr * PSTRB + c4b,
              (const char*)(g_alo + (size_t)(m0 + rr) * D_) + c4b);
        cpa16(sbase + 2 * PTILEB + rr * PSTRB + c4b,
              (const char*)(g_WOhi + (size_t)(n0 + rr) * D_) + c4b);
        cpa16(sbase + 3 * PTILEB + rr * PSTRB + c4b,
              (const char*)(g_WOlo + (size_t)(n0 + rr) * D_) + c4b);
    }
    CP_COMMIT();

    for (int c = 0; c < NCH; c++) {
        if (c + 1 < NCH) {
            uint32_t st = ((c + 1) & 1) * WSTGB;
            int kb = (c + 1) * 64;
#pragma unroll
            for (int it = 0; it < 2; it++) {
                int rr = r0 + it * 64;
                cpa16(sbase + st + rr * PSTRB + c4b,
                      (const char*)(g_ahi + (size_t)(m0 + rr) * D_) + kb + c4b);
                cpa16(sbase + st + PTILEB + rr * PSTRB + c4b,
                      (const char*)(g_alo + (size_t)(m0 + rr) * D_) + kb + c4b);
                cpa16(sbase + st + 2 * PTILEB + rr * PSTRB + c4b,
                      (const char*)(g_WOhi + (size_t)(n0 + rr) * D_) + kb + c4b);
                cpa16(sbase + st + 3 * PTILEB + rr * PSTRB + c4b,
                      (const char*)(g_WOlo + (size_t)(n0 + rr) * D_) + kb + c4b);
            }
            CP_COMMIT();
            CP_WAIT(1);
        } else {
            CP_WAIT(0);
        }
        __syncthreads();
        uint32_t off = (c & 1) * WSTGB;
        uint32_t ah_base = sbase + off + a_off;
        uint32_t al_base = sbase + off + PTILEB + a_off;
        uint32_t bh_base = sbase + off + 2 * PTILEB + b_off;
        uint32_t bl_base = sbase + off + 3 * PTILEB + b_off;
#pragma unroll
        for (int kk = 0; kk < 2; kk++) {
            uint32_t afh[4][4], afl[4][4], bh[2][4], bl[2][4];
#pragma unroll
            for (int mt = 0; mt < 4; mt++) {
                ldsm_x4(afh[mt], ah_base + mt * (16 * PSTRB) + kk * 32);
                ldsm_x4(afl[mt], al_base + mt * (16 * PSTRB) + kk * 32);
            }
#pragma unroll
            for (int j = 0; j < 2; j++) {
                ldsm_x4(bh[j], bh_base + j * (16 * PSTRB) + kk * 32);
                ldsm_x4(bl[j], bl_base + j * (16 * PSTRB) + kk * 32);
            }
#pragma unroll
            for (int nt = 0; nt < 4; nt++) {
                const uint32_t* bhp = &bh[nt >> 1][(nt & 1) * 2];
                const uint32_t* blp = &bl[nt >> 1][(nt & 1) * 2];
#pragma unroll
                for (int mt = 0; mt < 4; mt++) {
                    mma_bf16(acc[mt][nt], afh[mt], bhp);
                    mma_bf16(acc[mt][nt], afh[mt], blp);
                    mma_bf16(acc[mt][nt], afl[mt], bhp);
                }
            }
        }
        __syncthreads();
    }
#pragma unroll
    for (int mt = 0; mt < 4; mt++)
#pragma unroll
        for (int nt = 0; nt < 4; nt++) {
            int r = m0 + wm + mt * 16 + gid;
            int c = n0 + wn + nt * 8 + tig * 2;
            *(float2*)(out + (size_t)r * D_ + c) = make_float2(acc[mt][nt][0], acc[mt][nt][1]);
            *(float2*)(out + (size_t)(r + 8) * D_ + c) = make_float2(acc[mt][nt][2], acc[mt][nt][3]);
        }
}

// ---------------- launch ----------------
extern "C" void kernel_launch(void* const* d_in, const int* in_sizes, int n_in,
                              void* d_out, int out_size) {
    (void)in_sizes; (void)n_in; (void)out_size;
    const float* x   = (const float*)d_in[0];
    const float* qw  = (const float*)d_in[1];
    const float* kw  = (const float*)d_in[2];
    const float* vw  = (const float*)d_in[3];
    const float* wow = (const float*)d_in[4];
    float* out = (float*)d_out;

    const int PROJ_SMEM = 2 * PSTGB;   // 61440
    const int WO_SMEM   = 2 * WSTGB;   // 81920
    cudaFuncSetAttribute(attn_k, cudaFuncAttributeMaxDynamicSharedMemorySize, ATTN_SMEM_B);
    cudaFuncSetAttribute(gemm_proj_k, cudaFuncAttributeMaxDynamicSharedMemorySize, PROJ_SMEM);
    cudaFuncSetAttribute(gemm_wo_k, cudaFuncAttributeMaxDynamicSharedMemorySize, WO_SMEM);

    pack_w_k<<<(NCAT_ * D_ + 255) / 256, 256>>>(qw, kw, vw, wow);
    lif_x_k<<<(BCD_ + 255) / 256, 256>>>(x);
    gemm_proj_k<<<dim3(NCAT_ / 128, M_ / 128), 256, PROJ_SMEM>>>();
    lif_proj8_k<<<(BC_ * (NCAT_ / 4) + 255) / 256, 256>>>();
    attn_k<<<dim3(C_ / 128, T_ * B_ * H_), 256, ATTN_SMEM_B>>>();
    gemm_wo_k<<<dim3(D_ / 128, M_ / 128), 256, WO_SMEM>>>(out);
}

// round 13
// speedup vs baseline: 1.2530x; 1.0225x over previous
#include <cuda_runtime.h>
#include <cuda_bf16.h>
#include <cstdint>

#define T_ 4
#define B_ 8
#define C_ 512
#define D_ 768
#define H_ 8
#define HD_ 96
#define MKV_ 192
#define NCAT_ 1152            // 768 (q) + 192 (k) + 192 (v)
#define BC_ 4096              // B*C
#define M_ 16384              // T*B*C
#define BCD_ 3145728          // B*C*D

// ---------------- scratch (device globals: no allocation allowed) ----------
__device__ __nv_bfloat16 g_xs[M_ * D_];        // proj_lif spikes (exact 0/1)
__device__ __nv_bfloat16 g_Whi[NCAT_ * D_];    // concat [q_w; k_w; v_w] hi
__device__ __nv_bfloat16 g_Wlo[NCAT_ * D_];    // lo residual
__device__ __nv_bfloat16 g_WOhi[D_ * D_];
__device__ __nv_bfloat16 g_WOlo[D_ * D_];
__device__ __nv_bfloat16 g_sp[M_ * NCAT_];     // q/k/v spikes (bf16 0/1, exact)
__device__ __nv_bfloat16 g_ahi[M_ * D_];       // attention output hi
__device__ __nv_bfloat16 g_alo[M_ * D_];       // attention output lo

// ---------------- helpers ----------------
__device__ __forceinline__ uint32_t smem_u32(const void* p) {
    uint32_t a;
    asm("{ .reg .u64 t; cvta.to.shared.u64 t, %1; cvt.u32.u64 %0, t; }" : "=r"(a) : "l"(p));
    return a;
}
__device__ __forceinline__ void mma_bf16(float* c, const uint32_t* a, const uint32_t* b) {
    asm volatile(
        "mma.sync.aligned.m16n8k16.row.col.f32.bf16.bf16.f32 "
        "{%0,%1,%2,%3},{%4,%5,%6,%7},{%8,%9},{%0,%1,%2,%3};\n"
        : "+f"(c[0]), "+f"(c[1]), "+f"(c[2]), "+f"(c[3])
        : "r"(a[0]), "r"(a[1]), "r"(a[2]), "r"(a[3]), "r"(b[0]), "r"(b[1]));
}
__device__ __forceinline__ void ldsm_x4(uint32_t* r, uint32_t addr) {
    asm volatile("ldmatrix.sync.aligned.m8n8.x4.shared.b16 {%0,%1,%2,%3}, [%4];"
        : "=r"(r[0]), "=r"(r[1]), "=r"(r[2]), "=r"(r[3]) : "r"(addr));
}
__device__ __forceinline__ void ldsm_x4_t(uint32_t* r, uint32_t addr) {
    asm volatile("ldmatrix.sync.aligned.m8n8.x4.trans.shared.b16 {%0,%1,%2,%3}, [%4];"
        : "=r"(r[0]), "=r"(r[1]), "=r"(r[2]), "=r"(r[3]) : "r"(addr));
}
__device__ __forceinline__ void ldsm_x2_t(uint32_t* r, uint32_t addr) {
    asm volatile("ldmatrix.sync.aligned.m8n8.x2.trans.shared.b16 {%0,%1}, [%2];"
        : "=r"(r[0]), "=r"(r[1]) : "r"(addr));
}
__device__ __forceinline__ void cpa16(uint32_t dst, const void* src) {
    asm volatile("cp.async.ca.shared.global [%0], [%1], 16;" :: "r"(dst), "l"(src));
}
#define CP_COMMIT()  asm volatile("cp.async.commit_group;" ::: "memory")
#define CP_WAIT(n)   asm volatile("cp.async.wait_group %0;" :: "n"(n) : "memory")

// ---------------- kernel 1: split weights into bf16 hi/lo ----------------
__global__ void pack_w_k(const float* __restrict__ qw, const float* __restrict__ kw,
                         const float* __restrict__ vw, const float* __restrict__ wow) {
    int i = blockIdx.x * 256 + threadIdx.x;
    if (i < NCAT_ * D_) {
        int n = i / D_, k = i - n * D_;
        float w;
        if (n < D_)            w = qw[i];
        else if (n < D_ + MKV_) w = kw[(n - D_) * D_ + k];
        else                    w = vw[(n - D_ - MKV_) * D_ + k];
        __nv_bfloat16 hi = __float2bfloat16(w);
        g_Whi[i] = hi;
        g_Wlo[i] = __float2bfloat16(w - __bfloat162float(hi));
    }
    if (i < D_ * D_) {
        float w = wow[i];
        __nv_bfloat16 hi = __float2bfloat16(w);
        g_WOhi[i] = hi;
        g_WOlo[i] = __float2bfloat16(w - __bfloat162float(hi));
    }
}

// ---------------- kernel 2: LIF on x -> xs spikes (bf16 exact) -------------
__global__ void lif_x_k(const float* __restrict__ x) {
    int i = blockIdx.x * 256 + threadIdx.x;
    if (i >= BCD_) return;
    float v = 0.f;
#pragma unroll
    for (int t = 0; t < T_; t++) {
        v = v * 0.5f + x[t * BCD_ + i];
        bool s = (v >= 1.0f);
        g_xs[t * BCD_ + i] = __float2bfloat16(s ? 1.f : 0.f);
        if (s) v = 0.f;
    }
}

// ====== kernel 3: FUSED projection GEMM + LIF (membrane-in-accumulator) ====
// Grid (9, 32): n-block x bc-block; loop t inside. acc carries 0.5*v between
// t sweeps; MMA accumulates pre_t on top -> acc = v_t. Zero extra footprint.
#define PSTR 40                 // smem row stride, bf16 units
#define PSTRB 80                // ... bytes
#define PTILE (128 * PSTR)      // tile bf16 units
#define PTILEB (128 * PSTRB)    // tile bytes (10240)
#define PSTGB (3 * PTILEB)      // 30720
#define NCH 24                  // K=768 / 32
__global__ void __launch_bounds__(256, 2)
gemm_proj_fused() {
    extern __shared__ __nv_bfloat16 smp[];
    uint32_t sbase = smem_u32(smp);
    int tid = threadIdx.x;
    int lane = tid & 31, warp = tid >> 5;
    int gid = lane >> 2, tig = lane & 3;
    int wm = (warp >> 2) * 64, wn = (warp & 3) * 32;
    int m0 = blockIdx.y * 128;            // within one t-slice (BC rows)
    int n0 = blockIdx.x * 128;

    uint32_t a_off = (wm + (lane & 15)) * PSTRB + (lane >> 4) * 16;
    uint32_t b_off = (wn + ((lane >> 4) << 3) + (lane & 7)) * PSTRB + ((lane >> 3) & 1) * 16;

    float acc[4][4][4];                   // doubles as LIF membrane (x0.5)
#pragma unroll
    for (int a = 0; a < 4; a++)
#pragma unroll
        for (int b = 0; b < 4; b++)
#pragma unroll
            for (int c = 0; c < 4; c++) acc[a][b][c] = 0.f;

    int r0 = tid >> 2, c4b = (tid & 3) * 16;

    for (int t = 0; t < T_; t++) {
        size_t mrow = (size_t)(t * BC_ + m0);
        // prologue: chunk 0 -> stage 0
#pragma unroll
        for (int it = 0; it < 2; it++) {
            int rr = r0 + it * 64;
            cpa16(sbase + rr * PSTRB + c4b,
                  (const char*)(g_xs + (mrow + rr) * D_) + c4b);
            cpa16(sbase + PTILEB + rr * PSTRB + c4b,
                  (const char*)(g_Whi + (size_t)(n0 + rr) * D_) + c4b);
            cpa16(sbase + 2 * PTILEB + rr * PSTRB + c4b,
                  (const char*)(g_Wlo + (size_t)(n0 + rr) * D_) + c4b);
        }
        CP_COMMIT();

        for (int c = 0; c < NCH; c++) {
            if (c + 1 < NCH) {
                uint32_t st = ((c + 1) & 1) * PSTGB;
                int kb = (c + 1) * 64;
#pragma unroll
                for (int it = 0; it < 2; it++) {
                    int rr = r0 + it * 64;
                    cpa16(sbase + st + rr * PSTRB + c4b,
                          (const char*)(g_xs + (mrow + rr) * D_) + kb + c4b);
                    cpa16(sbase + st + PTILEB + rr * PSTRB + c4b,
                          (const char*)(g_Whi + (size_t)(n0 + rr) * D_) + kb + c4b);
                    cpa16(sbase + st + 2 * PTILEB + rr * PSTRB + c4b,
                          (const char*)(g_Wlo + (size_t)(n0 + rr) * D_) + kb + c4b);
                }
                CP_COMMIT();
                CP_WAIT(1);
            } else {
                CP_WAIT(0);
            }
            __syncthreads();
            uint32_t off = (c & 1) * PSTGB;
            uint32_t a_base = sbase + off + a_off;
            uint32_t bh_base = sbase + off + PTILEB + b_off;
            uint32_t bl_base = sbase + off + 2 * PTILEB + b_off;
#pragma unroll
            for (int kk = 0; kk < 2; kk++) {
                uint32_t af[4][4], bh[2][4], bl[2][4];
#pragma unroll
                for (int mt = 0; mt < 4; mt++)
                    ldsm_x4(af[mt], a_base + mt * (16 * PSTRB) + kk * 32);
#pragma unroll
                for (int j = 0; j < 2; j++) {
                    ldsm_x4(bh[j], bh_base + j * (16 * PSTRB) + kk * 32);
                    ldsm_x4(bl[j], bl_base + j * (16 * PSTRB) + kk * 32);
                }
#pragma unroll
                for (int nt = 0; nt < 4; nt++) {
                    const uint32_t* bhp = &bh[nt >> 1][(nt & 1) * 2];
                    const uint32_t* blp = &bl[nt >> 1][(nt & 1) * 2];
#pragma unroll
                    for (int mt = 0; mt < 4; mt++) {
                        mma_bf16(acc[mt][nt], af[mt], bhp);
                        mma_bf16(acc[mt][nt], af[mt], blp);
                    }
                }
            }
            __syncthreads();
        }

        // LIF epilogue for this t: acc == v_t. Emit spikes, set acc = 0.5*v'.
#pragma unroll
        for (int mt = 0; mt < 4; mt++)
#pragma unroll
            for (int nt = 0; nt < 4; nt++) {
                int col = n0 + wn + nt * 8 + tig * 2;
                uint32_t w[2];
#pragma unroll
                for (int half = 0; half < 2; half++) {
                    uint32_t pk = 0;
#pragma unroll
                    for (int j = 0; j < 2; j++) {
                        int i = half * 2 + j;
                        float v = acc[mt][nt][i];
                        bool sp = (v >= 1.0f);
                        if (sp) pk |= 0x3F80u << (j * 16);
                        acc[mt][nt][i] = sp ? 0.f : v * 0.5f;
                    }
                    w[half] = pk;
                }
                size_t r = mrow + wm + mt * 16 + gid;
                *(uint32_t*)(g_sp + r * NCAT_ + col) = w[0];
                *(uint32_t*)(g_sp + (r + 8) * NCAT_ + col) = w[1];
            }
    }
}

// ---------------- kernel 4: bf16 attention, V via ldmatrix.trans -----------
// smem bytes: Q[128x208]=26624 | K0,K1[128x208] | V0,V1[128x208] | S[128x272]
#define AOK0 26624
#define AOV0 (26624 * 3)           // 79872
#define AOS  (26624 * 5)           // 133120
#define ATTN_SMEM_B (AOS + 34816)  // 167936
__global__ void __launch_bounds__(256)
attn_k() {
    extern __shared__ char smA[];
    uint32_t sb = smem_u32(smA);
    __nv_bfloat16* sS = (__nv_bfloat16*)(smA + AOS);

    int tid = threadIdx.x, lane = tid & 31, warp = tid >> 5;
    int gid = lane >> 2, tig = lane & 3;
    int wm = (warp >> 2) * 64;
    int wn1 = (warp & 3) * 32;  // key cols in mma1
    int wn2 = (warp & 3) * 24;  // d cols in mma2
    int qb = blockIdx.x;        // q row block (0..3)
    int tbh = blockIdx.y;       // (t*B+b)*H + h
    int h = tbh & 7, tb = tbh >> 3;
    int kvh = h >> 2;
    int qcol = h * HD_;
    int kcol = D_ + kvh * HD_;
    int vcol = D_ + MKV_ + kvh * HD_;
    int rowbase = tb * C_;

    uint32_t q_base = sb + (wm + (lane & 15)) * 208 + (lane >> 4) * 16;
    uint32_t k_off = (wn1 + ((lane >> 4) << 3) + (lane & 7)) * 208 + ((lane >> 3) & 1) * 16;
    uint32_t s_base = sb + AOS + (wm + (lane & 15)) * 272 + (lane >> 4) * 16;
    uint32_t v4_off = (lane & 15) * 208 + wn2 * 2 + (lane >> 4) * 16;
    uint32_t v2_off = (lane & 15) * 208 + (wn2 + 16) * 2;
    uint32_t k_stage[2] = { sb + AOK0 + k_off, sb + AOK0 + 26624 + k_off };
    uint32_t v4_stage[2] = { sb + AOV0 + v4_off, sb + AOV0 + 26624 + v4_off };
    uint32_t v2_stage[2] = { sb + AOV0 + v2_off, sb + AOV0 + 26624 + v2_off };

    // prologue: Q + K(kc=0) + V(kc=0), one commit group
#pragma unroll
    for (int it = 0; it < 6; it++) {
        int idx = tid + it * 256;
        int r = idx / 12, c = idx % 12;
        cpa16(sb + r * 208 + c * 16,
              (const char*)(g_sp + (size_t)(rowbase + qb * 128 + r) * NCAT_ + qcol) + c * 16);
    }
#pragma unroll
    for (int it = 0; it < 6; it++) {
        int idx = tid + it * 256;
        int r = idx / 12, c = idx % 12;
        cpa16(sb + AOK0 + r * 208 + c * 16,
              (const char*)(g_sp + (size_t)(rowbase + r) * NCAT_ + kcol) + c * 16);
    }
#pragma unroll
    for (int it = 0; it < 6; it++) {
        int idx = tid + it * 256;
        int r = idx / 12, c = idx % 12;
        cpa16(sb + AOV0 + r * 208 + c * 16,
              (const char*)(g_sp + (size_t)(rowbase + r) * NCAT_ + vcol) + c * 16);
    }
    CP_COMMIT();

    float acc2[4][3][4];
#pragma unroll
    for (int a = 0; a < 4; a++)
#pragma unroll
        for (int b = 0; b < 3; b++)
#pragma unroll
            for (int c = 0; c < 4; c++) acc2[a][b][c] = 0.f;

    for (int kc = 0; kc < 4; kc++) {
        if (kc + 1 < 4) {
            uint32_t kst = sb + AOK0 + ((kc + 1) & 1) * 26624;
            uint32_t vst = sb + AOV0 + ((kc + 1) & 1) * 26624;
#pragma unroll
            for (int it = 0; it < 6; it++) {
                int idx = tid + it * 256;
                int r = idx / 12, c = idx % 12;
                cpa16(kst + r * 208 + c * 16,
                      (const char*)(g_sp + (size_t)(rowbase + (kc + 1) * 128 + r) * NCAT_ + kcol) + c * 16);
            }
#pragma unroll
            for (int it = 0; it < 6; it++) {
                int idx = tid + it * 256;
                int r = idx / 12, c = idx % 12;
                cpa16(vst + r * 208 + c * 16,
                      (const char*)(g_sp + (size_t)(rowbase + (kc + 1) * 128 + r) * NCAT_ + vcol) + c * 16);
            }
            CP_COMMIT();
            CP_WAIT(1);
        } else {
            CP_WAIT(0);
        }
        __syncthreads();
        int st = kc & 1;

        // mma1: counts = q @ k^T   (128 x 128, K=96) — exact integers
        float acc1[4][4][4];
#pragma unroll
        for (int a = 0; a < 4; a++)
#pragma unroll
            for (int b = 0; b < 4; b++)
#pragma unroll
                for (int c = 0; c < 4; c++) acc1[a][b][c] = 0.f;
#pragma unroll
        for (int kk = 0; kk < 6; kk++) {
            uint32_t af[4][4], bk[2][4];
#pragma unroll
            for (int mt = 0; mt < 4; mt++)
                ldsm_x4(af[mt], q_base + mt * (16 * 208) + kk * 32);
#pragma unroll
            for (int j = 0; j < 2; j++)
                ldsm_x4(bk[j], k_stage[st] + j * (16 * 208) + kk * 32);
#pragma unroll
            for (int nt = 0; nt < 4; nt++) {
                const uint32_t* bb = &bk[nt >> 1][(nt & 1) * 2];
#pragma unroll
                for (int mt = 0; mt < 4; mt++) mma_bf16(acc1[mt][nt], af[mt], bb);
            }
        }
        // store counts to smem as bf16 (exact: <=96)
#pragma unroll
        for (int mt = 0; mt < 4; mt++)
#pragma unroll
            for (int nt = 0; nt < 4; nt++) {
                int r = wm + mt * 16 + gid;
                int cc = wn1 + nt * 8 + tig * 2;
                __nv_bfloat162 p0, p1;
                p0.x = __float2bfloat16(acc1[mt][nt][0]);
                p0.y = __float2bfloat16(acc1[mt][nt][1]);
                p1.x = __float2bfloat16(acc1[mt][nt][2]);
                p1.y = __float2bfloat16(acc1[mt][nt][3]);
                *(__nv_bfloat162*)(sS + r * 136 + cc) = p0;
                *(__nv_bfloat162*)(sS + (r + 8) * 136 + cc) = p1;
            }
        __syncthreads();

        // mma2: acc2 += counts @ v   (128 x 96, K=128) — exact integers
#pragma unroll
        for (int kk = 0; kk < 8; kk++) {
            uint32_t af[4][4], bv[6];
#pragma unroll
            for (int mt = 0; mt < 4; mt++)
                ldsm_x4(af[mt], s_base + mt * (16 * 272) + kk * 32);
            ldsm_x4_t(bv, v4_stage[st] + kk * (16 * 208));      // nt0, nt1
            ldsm_x2_t(bv + 4, v2_stage[st] + kk * (16 * 208));  // nt2
#pragma unroll
            for (int nt = 0; nt < 3; nt++) {
                const uint32_t* bb = &bv[nt * 2];
#pragma unroll
                for (int mt = 0; mt < 4; mt++) mma_bf16(acc2[mt][nt], af[mt], bb);
            }
        }
        __syncthreads();
    }

    // epilogue: scale by 0.1, hi/lo split for the wo GEMM
#pragma unroll
    for (int mt = 0; mt < 4; mt++)
#pragma unroll
        for (int nt = 0; nt < 3; nt++) {
            int r = rowbase + qb * 128 + wm + mt * 16 + gid;
            int cb = qcol + wn2 + nt * 8 + tig * 2;
#pragma unroll
            for (int half = 0; half < 2; half++) {
                int rr = r + half * 8;
                float v0 = 0.1f * acc2[mt][nt][half * 2 + 0];
                float v1 = 0.1f * acc2[mt][nt][half * 2 + 1];
                __nv_bfloat162 hi2, lo2;
                hi2.x = __float2bfloat16(v0);
                hi2.y = __float2bfloat16(v1);
                lo2.x = __float2bfloat16(v0 - __bfloat162float(hi2.x));
                lo2.y = __float2bfloat16(v1 - __bfloat162float(hi2.y));
                *(__nv_bfloat162*)(g_ahi + (size_t)rr * D_ + cb) = hi2;
                *(__nv_bfloat162*)(g_alo + (size_t)rr * D_ + cb) = lo2;
            }
        }
}

// ---------------- kernel 5: output GEMM  d_out = attn @ wo^T ----------------
// r8 (WIN): cp.async.ca double buffer; A/B hi/lo -> 3 MMAs per k-step.
#define WSTGB (4 * PTILEB)     // 40960
__global__ void __launch_bounds__(256)
gemm_wo_k(float* __restrict__ out) {
    extern __shared__ __nv_bfloat16 smw[];
    uint32_t sbase = smem_u32(smw);
    int tid = threadIdx.x;
    int lane = tid & 31, warp = tid >> 5;
    int gid = lane >> 2, tig = lane & 3;
    int wm = (warp >> 2) * 64, wn = (warp & 3) * 32;
    int m0 = blockIdx.y * 128, n0 = blockIdx.x * 128;

    uint32_t a_off = (wm + (lane & 15)) * PSTRB + (lane >> 4) * 16;
    uint32_t b_off = (wn + ((lane >> 4) << 3) + (lane & 7)) * PSTRB + ((lane >> 3) & 1) * 16;

    float acc[4][4][4];
#pragma unroll
    for (int a = 0; a < 4; a++)
#pragma unroll
        for (int b = 0; b < 4; b++)
#pragma unroll
            for (int c = 0; c < 4; c++) acc[a][b][c] = 0.f;

    int r0 = tid >> 2, c4b = (tid & 3) * 16;

#pragma unroll
    for (int it = 0; it < 2; it++) {
        int rr = r0 + it * 64;
        cpa16(sbase + rr * PSTRB + c4b,
              (const char*)(g_ahi + (size_t)(m0 + rr) * D_) + c4b);
        cpa16(sbase + PTILEB + rr * PSTRB + c4b,
              (const char*)(g_alo + (size_t)(m0 + rr) * D_) + c4b);
        cpa16(sbase + 2 * PTILEB + rr * PSTRB + c4b,
              (const char*)(g_WOhi + (size_t)(n0 + rr) * D_) + c4b);
        cpa16(sbase + 3 * PTILEB + rr * PSTRB + c4b,
              (const char*)(g_WOlo + (size_t)(n0 + rr) * D_) + c4b);
    }
    CP_COMMIT();

    for (int c = 0; c < NCH; c++) {
        if (c + 1 < NCH) {
            uint32_t st = ((c + 1) & 1) * WSTGB;
            int kb = (c + 1) * 64;
#pragma unroll
            for (int it = 0; it < 2; it++) {
                int rr = r0 + it * 64;
                cpa16(sbase + st + rr * PSTRB + c4b,
                      (const char*)(g_ahi + (size_t)(m0 + rr) * D_) + kb + c4b);
                cpa16(sbase + st + PTILEB + rr * PSTRB + c4b,
                      (const char*)(g_alo + (size_t)(m0 + rr) * D_) + kb + c4b);
                cpa16(sbase + st + 2 * PTILEB + rr * PSTRB + c4b,
                      (const char*)(g_WOhi + (size_t)(n0 + rr) * D_) + kb + c4b);
                cpa16(sbase + st + 3 * PTILEB + rr * PSTRB + c4b,
                      (const char*)(g_WOlo + (size_t)(n0 + rr) * D_) + kb + c4b);
            }
            CP_COMMIT();
            CP_WAIT(1);
        } else {
            CP_WAIT(0);
        }
        __syncthreads();
        uint32_t off = (c & 1) * WSTGB;
        uint32_t ah_base = sbase + off + a_off;
        uint32_t al_base = sbase + off + PTILEB + a_off;
        uint32_t bh_base = sbase + off + 2 * PTILEB + b_off;
        uint32_t bl_base = sbase + off + 3 * PTILEB + b_off;
#pragma unroll
        for (int kk = 0; kk < 2; kk++) {
            uint32_t afh[4][4], afl[4][4], bh[2][4], bl[2][4];
#pragma unroll
            for (int mt = 0; mt < 4; mt++) {
                ldsm_x4(afh[mt], ah_base + mt * (16 * PSTRB) + kk * 32);
                ldsm_x4(afl[mt], al_base + mt * (16 * PSTRB) + kk * 32);
            }
#pragma unroll
            for (int j = 0; j < 2; j++) {
                ldsm_x4(bh[j], bh_base + j * (16 * PSTRB) + kk * 32);
                ldsm_x4(bl[j], bl_base + j * (16 * PSTRB) + kk * 32);
            }
#pragma unroll
            for (int nt = 0; nt < 4; nt++) {
                const uint32_t* bhp = &bh[nt >> 1][(nt & 1) * 2];
                const uint32_t* blp = &bl[nt >> 1][(nt & 1) * 2];
#pragma unroll
                for (int mt = 0; mt < 4; mt++) {
                    mma_bf16(acc[mt][nt], afh[mt], bhp);
                    mma_bf16(acc[mt][nt], afh[mt], blp);
                    mma_bf16(acc[mt][nt], afl[mt], bhp);
                }
            }
        }
        __syncthreads();
    }
#pragma unroll
    for (int mt = 0; mt < 4; mt++)
#pragma unroll
        for (int nt = 0; nt < 4; nt++) {
            int r = m0 + wm + mt * 16 + gid;
            int c = n0 + wn + nt * 8 + tig * 2;
            *(float2*)(out + (size_t)r * D_ + c) = make_float2(acc[mt][nt][0], acc[mt][nt][1]);
            *(float2*)(out + (size_t)(r + 8) * D_ + c) = make_float2(acc[mt][nt][2], acc[mt][nt][3]);
        }
}

// ---------------- launch ----------------
extern "C" void kernel_launch(void* const* d_in, const int* in_sizes, int n_in,
                              void* d_out, int out_size) {
    (void)in_sizes; (void)n_in; (void)out_size;
    const float* x   = (const float*)d_in[0];
    const float* qw  = (const float*)d_in[1];
    const float* kw  = (const float*)d_in[2];
    const float* vw  = (const float*)d_in[3];
    const float* wow = (const float*)d_in[4];
    float* out = (float*)d_out;

    const int PROJ_SMEM = 2 * PSTGB;   // 61440
    const int WO_SMEM   = 2 * WSTGB;   // 81920
    cudaFuncSetAttribute(attn_k, cudaFuncAttributeMaxDynamicSharedMemorySize, ATTN_SMEM_B);
    cudaFuncSetAttribute(gemm_proj_fused, cudaFuncAttributeMaxDynamicSharedMemorySize, PROJ_SMEM);
    cudaFuncSetAttribute(gemm_wo_k, cudaFuncAttributeMaxDynamicSharedMemorySize, WO_SMEM);

    pack_w_k<<<(NCAT_ * D_ + 255) / 256, 256>>>(qw, kw, vw, wow);
    lif_x_k<<<(BCD_ + 255) / 256, 256>>>(x);
    gemm_proj_fused<<<dim3(NCAT_ / 128, BC_ / 128), 256, PROJ_SMEM>>>();
    attn_k<<<dim3(C_ / 128, T_ * B_ * H_), 256, ATTN_SMEM_B>>>();
    gemm_wo_k<<<dim3(D_ / 128, M_ / 128), 256, WO_SMEM>>>(out);
}

// round 14
// speedup vs baseline: 1.2685x; 1.0124x over previous
#include <cuda_runtime.h>
#include <cuda_bf16.h>
#include <cstdint>

#define T_ 4
#define B_ 8
#define C_ 512
#define D_ 768
#define H_ 8
#define HD_ 96
#define MKV_ 192
#define NCAT_ 1152            // 768 (q) + 192 (k) + 192 (v)
#define BC_ 4096              // B*C
#define M_ 16384              // T*B*C
#define BCD_ 3145728          // B*C*D

// ---------------- scratch (device globals: no allocation allowed) ----------
__device__ __nv_bfloat16 g_xs[M_ * D_];        // proj_lif spikes (exact 0/1)
__device__ __nv_bfloat16 g_Whi[NCAT_ * D_];    // concat [q_w; k_w; v_w] hi
__device__ __nv_bfloat16 g_Wlo[NCAT_ * D_];    // lo residual
__device__ __nv_bfloat16 g_WOhi[D_ * D_];
__device__ __nv_bfloat16 g_WOlo[D_ * D_];
__device__ __nv_bfloat16 g_sp[M_ * NCAT_];     // q/k/v spikes (bf16 0/1, exact)
__device__ __nv_bfloat16 g_ahi[M_ * D_];       // attention output hi
__device__ __nv_bfloat16 g_alo[M_ * D_];       // attention output lo

// ---------------- helpers ----------------
__device__ __forceinline__ uint32_t smem_u32(const void* p) {
    uint32_t a;
    asm("{ .reg .u64 t; cvta.to.shared.u64 t, %1; cvt.u32.u64 %0, t; }" : "=r"(a) : "l"(p));
    return a;
}
__device__ __forceinline__ void mma_bf16(float* c, const uint32_t* a, const uint32_t* b) {
    asm volatile(
        "mma.sync.aligned.m16n8k16.row.col.f32.bf16.bf16.f32 "
        "{%0,%1,%2,%3},{%4,%5,%6,%7},{%8,%9},{%0,%1,%2,%3};\n"
        : "+f"(c[0]), "+f"(c[1]), "+f"(c[2]), "+f"(c[3])
        : "r"(a[0]), "r"(a[1]), "r"(a[2]), "r"(a[3]), "r"(b[0]), "r"(b[1]));
}
__device__ __forceinline__ void ldsm_x4(uint32_t* r, uint32_t addr) {
    asm volatile("ldmatrix.sync.aligned.m8n8.x4.shared.b16 {%0,%1,%2,%3}, [%4];"
        : "=r"(r[0]), "=r"(r[1]), "=r"(r[2]), "=r"(r[3]) : "r"(addr));
}
__device__ __forceinline__ void ldsm_x4_t(uint32_t* r, uint32_t addr) {
    asm volatile("ldmatrix.sync.aligned.m8n8.x4.trans.shared.b16 {%0,%1,%2,%3}, [%4];"
        : "=r"(r[0]), "=r"(r[1]), "=r"(r[2]), "=r"(r[3]) : "r"(addr));
}
__device__ __forceinline__ uint32_t pack_bf16x2(float lo, float hi) {
    uint32_t r;
    asm("cvt.rn.bf16x2.f32 %0, %1, %2;" : "=r"(r) : "f"(hi), "f"(lo));
    return r;
}
__device__ __forceinline__ void cpa16(uint32_t dst, const void* src) {
    asm volatile("cp.async.ca.shared.global [%0], [%1], 16;" :: "r"(dst), "l"(src));
}
#define CP_COMMIT()  asm volatile("cp.async.commit_group;" ::: "memory")
#define CP_WAIT(n)   asm volatile("cp.async.wait_group %0;" :: "n"(n) : "memory")

// ---------------- kernel 1: split weights into bf16 hi/lo ----------------
__global__ void pack_w_k(const float* __restrict__ qw, const float* __restrict__ kw,
                         const float* __restrict__ vw, const float* __restrict__ wow) {
    int i = blockIdx.x * 256 + threadIdx.x;
    if (i < NCAT_ * D_) {
        int n = i / D_, k = i - n * D_;
        float w;
        if (n < D_)            w = qw[i];
        else if (n < D_ + MKV_) w = kw[(n - D_) * D_ + k];
        else                    w = vw[(n - D_ - MKV_) * D_ + k];
        __nv_bfloat16 hi = __float2bfloat16(w);
        g_Whi[i] = hi;
        g_Wlo[i] = __float2bfloat16(w - __bfloat162float(hi));
    }
    if (i < D_ * D_) {
        float w = wow[i];
        __nv_bfloat16 hi = __float2bfloat16(w);
        g_WOhi[i] = hi;
        g_WOlo[i] = __float2bfloat16(w - __bfloat162float(hi));
    }
}

// ---------------- kernel 2: LIF on x -> xs spikes (bf16 exact) -------------
__global__ void lif_x_k(const float* __restrict__ x) {
    int i = blockIdx.x * 256 + threadIdx.x;
    if (i >= BCD_) return;
    float v = 0.f;
#pragma unroll
    for (int t = 0; t < T_; t++) {
        v = v * 0.5f + x[t * BCD_ + i];
        bool s = (v >= 1.0f);
        g_xs[t * BCD_ + i] = __float2bfloat16(s ? 1.f : 0.f);
        if (s) v = 0.f;
    }
}

// ====== kernel 3: FUSED projection GEMM + LIF (membrane-in-accumulator) ====
#define PSTR 40                 // smem row stride, bf16 units
#define PSTRB 80                // ... bytes
#define PTILE (128 * PSTR)      // tile bf16 units
#define PTILEB (128 * PSTRB)    // tile bytes (10240)
#define PSTGB (3 * PTILEB)      // 30720
#define NCH 24                  // K=768 / 32
__global__ void __launch_bounds__(256, 2)
gemm_proj_fused() {
    extern __shared__ __nv_bfloat16 smp[];
    uint32_t sbase = smem_u32(smp);
    int tid = threadIdx.x;
    int lane = tid & 31, warp = tid >> 5;
    int gid = lane >> 2, tig = lane & 3;
    int wm = (warp >> 2) * 64, wn = (warp & 3) * 32;
    int m0 = blockIdx.y * 128;            // within one t-slice (BC rows)
    int n0 = blockIdx.x * 128;

    uint32_t a_off = (wm + (lane & 15)) * PSTRB + (lane >> 4) * 16;
    uint32_t b_off = (wn + ((lane >> 4) << 3) + (lane & 7)) * PSTRB + ((lane >> 3) & 1) * 16;

    float acc[4][4][4];                   // doubles as LIF membrane (x0.5)
#pragma unroll
    for (int a = 0; a < 4; a++)
#pragma unroll
        for (int b = 0; b < 4; b++)
#pragma unroll
            for (int c = 0; c < 4; c++) acc[a][b][c] = 0.f;

    int r0 = tid >> 2, c4b = (tid & 3) * 16;

    for (int t = 0; t < T_; t++) {
        size_t mrow = (size_t)(t * BC_ + m0);
#pragma unroll
        for (int it = 0; it < 2; it++) {
            int rr = r0 + it * 64;
            cpa16(sbase + rr * PSTRB + c4b,
                  (const char*)(g_xs + (mrow + rr) * D_) + c4b);
            cpa16(sbase + PTILEB + rr * PSTRB + c4b,
                  (const char*)(g_Whi + (size_t)(n0 + rr) * D_) + c4b);
            cpa16(sbase + 2 * PTILEB + rr * PSTRB + c4b,
                  (const char*)(g_Wlo + (size_t)(n0 + rr) * D_) + c4b);
        }
        CP_COMMIT();

        for (int c = 0; c < NCH; c++) {
            if (c + 1 < NCH) {
                uint32_t st = ((c + 1) & 1) * PSTGB;
                int kb = (c + 1) * 64;
#pragma unroll
                for (int it = 0; it < 2; it++) {
                    int rr = r0 + it * 64;
                    cpa16(sbase + st + rr * PSTRB + c4b,
                          (const char*)(g_xs + (mrow + rr) * D_) + kb + c4b);
                    cpa16(sbase + st + PTILEB + rr * PSTRB + c4b,
                          (const char*)(g_Whi + (size_t)(n0 + rr) * D_) + kb + c4b);
                    cpa16(sbase + st + 2 * PTILEB + rr * PSTRB + c4b,
                          (const char*)(g_Wlo + (size_t)(n0 + rr) * D_) + kb + c4b);
                }
                CP_COMMIT();
                CP_WAIT(1);
            } else {
                CP_WAIT(0);
            }
            __syncthreads();
            uint32_t off = (c & 1) * PSTGB;
            uint32_t a_base = sbase + off + a_off;
            uint32_t bh_base = sbase + off + PTILEB + b_off;
            uint32_t bl_base = sbase + off + 2 * PTILEB + b_off;
#pragma unroll
            for (int kk = 0; kk < 2; kk++) {
                uint32_t af[4][4], bh[2][4], bl[2][4];
#pragma unroll
                for (int mt = 0; mt < 4; mt++)
                    ldsm_x4(af[mt], a_base + mt * (16 * PSTRB) + kk * 32);
#pragma unroll
                for (int j = 0; j < 2; j++) {
                    ldsm_x4(bh[j], bh_base + j * (16 * PSTRB) + kk * 32);
                    ldsm_x4(bl[j], bl_base + j * (16 * PSTRB) + kk * 32);
                }
#pragma unroll
                for (int nt = 0; nt < 4; nt++) {
                    const uint32_t* bhp = &bh[nt >> 1][(nt & 1) * 2];
                    const uint32_t* blp = &bl[nt >> 1][(nt & 1) * 2];
#pragma unroll
                    for (int mt = 0; mt < 4; mt++) {
                        mma_bf16(acc[mt][nt], af[mt], bhp);
                        mma_bf16(acc[mt][nt], af[mt], blp);
                    }
                }
            }
            __syncthreads();
        }

        // LIF epilogue for this t: acc == v_t. Emit spikes, set acc = 0.5*v'.
#pragma unroll
        for (int mt = 0; mt < 4; mt++)
#pragma unroll
            for (int nt = 0; nt < 4; nt++) {
                int col = n0 + wn + nt * 8 + tig * 2;
                uint32_t w[2];
#pragma unroll
                for (int half = 0; half < 2; half++) {
                    uint32_t pk = 0;
#pragma unroll
                    for (int j = 0; j < 2; j++) {
                        int i = half * 2 + j;
                        float v = acc[mt][nt][i];
                        bool sp = (v >= 1.0f);
                        if (sp) pk |= 0x3F80u << (j * 16);
                        acc[mt][nt][i] = sp ? 0.f : v * 0.5f;
                    }
                    w[half] = pk;
                }
                size_t r = mrow + wm + mt * 16 + gid;
                *(uint32_t*)(g_sp + r * NCAT_ + col) = w[0];
                *(uint32_t*)(g_sp + (r + 8) * NCAT_ + col) = w[1];
            }
    }
}

// ====== kernel 4: attention, register-resident P (FA2-style warp layout) ===
// Each warp owns 16 q-rows x ALL 128 keys. mma1 C-frags convert directly to
// mma2 A-frags (pack to bf16x2, exact ints <=96) — no S smem, one less sync.
// smem bytes: Q[128x208]=26624 | K0,K1[128x208] | V0,V1[128x208] = 133120
#define AOK0 26624
#define AOV0 (26624 * 3)
#define ATTN_SMEM_B (26624 * 5)
__global__ void __launch_bounds__(256)
attn_k() {
    extern __shared__ char smA[];
    uint32_t sb = smem_u32(smA);

    int tid = threadIdx.x, lane = tid & 31, warp = tid >> 5;
    int gid = lane >> 2, tig = lane & 3;
    int wm = warp * 16;         // 8 warps x 16 q-rows
    int qb = blockIdx.x;        // q row block (0..3)
    int tbh = blockIdx.y;       // (t*B+b)*H + h
    int h = tbh & 7, tb = tbh >> 3;
    int kvh = h >> 2;
    int qcol = h * HD_;
    int kcol = D_ + kvh * HD_;
    int vcol = D_ + MKV_ + kvh * HD_;
    int rowbase = tb * C_;

    // ldmatrix lane-address offsets
    uint32_t q_base = sb + (wm + (lane & 15)) * 208 + (lane >> 4) * 16;
    uint32_t k_off = (((lane >> 4) << 3) + (lane & 7)) * 208 + ((lane >> 3) & 1) * 16;
    uint32_t v_off = (lane & 15) * 208 + (lane >> 4) * 16;   // trans-ldsm
    uint32_t k_stage[2] = { sb + AOK0 + k_off, sb + AOK0 + 26624 + k_off };
    uint32_t v_stage[2] = { sb + AOV0 + v_off, sb + AOV0 + 26624 + v_off };

    // prologue: Q + K(kc=0) + V(kc=0), one commit group
#pragma unroll
    for (int it = 0; it < 6; it++) {
        int idx = tid + it * 256;
        int r = idx / 12, c = idx % 12;
        cpa16(sb + r * 208 + c * 16,
              (const char*)(g_sp + (size_t)(rowbase + qb * 128 + r) * NCAT_ + qcol) + c * 16);
    }
#pragma unroll
    for (int it = 0; it < 6; it++) {
        int idx = tid + it * 256;
        int r = idx / 12, c = idx % 12;
        cpa16(sb + AOK0 + r * 208 + c * 16,
              (const char*)(g_sp + (size_t)(rowbase + r) * NCAT_ + kcol) + c * 16);
    }
#pragma unroll
    for (int it = 0; it < 6; it++) {
        int idx = tid + it * 256;
        int r = idx / 12, c = idx % 12;
        cpa16(sb + AOV0 + r * 208 + c * 16,
              (const char*)(g_sp + (size_t)(rowbase + r) * NCAT_ + vcol) + c * 16);
    }
    CP_COMMIT();

    float acc2[12][4];          // 96 d-cols, 12 n-tiles
#pragma unroll
    for (int b = 0; b < 12; b++)
#pragma unroll
        for (int c = 0; c < 4; c++) acc2[b][c] = 0.f;

    for (int kc = 0; kc < 4; kc++) {
        if (kc + 1 < 4) {
            uint32_t kst = sb + AOK0 + ((kc + 1) & 1) * 26624;
            uint32_t vst = sb + AOV0 + ((kc + 1) & 1) * 26624;
#pragma unroll
            for (int it = 0; it < 6; it++) {
                int idx = tid + it * 256;
                int r = idx / 12, c = idx % 12;
                cpa16(kst + r * 208 + c * 16,
                      (const char*)(g_sp + (size_t)(rowbase + (kc + 1) * 128 + r) * NCAT_ + kcol) + c * 16);
            }
#pragma unroll
            for (int it = 0; it < 6; it++) {
                int idx = tid + it * 256;
                int r = idx / 12, c = idx % 12;
                cpa16(vst + r * 208 + c * 16,
                      (const char*)(g_sp + (size_t)(rowbase + (kc + 1) * 128 + r) * NCAT_ + vcol) + c * 16);
            }
            CP_COMMIT();
            CP_WAIT(1);
        } else {
            CP_WAIT(0);
        }
        __syncthreads();
        int st = kc & 1;

        // mma1: counts = q @ k^T  (16 rows x 128 keys, K=96) — exact integers
        float acc1[16][4];
#pragma unroll
        for (int b = 0; b < 16; b++)
#pragma unroll
            for (int c = 0; c < 4; c++) acc1[b][c] = 0.f;
#pragma unroll
        for (int kk = 0; kk < 6; kk++) {
            uint32_t aq[4];
            ldsm_x4(aq, q_base + kk * 32);
#pragma unroll
            for (int j = 0; j < 8; j++) {
                uint32_t bk[4];
                ldsm_x4(bk, k_stage[st] + j * (16 * 208) + kk * 32);
                mma_bf16(acc1[2 * j], aq, bk);
                mma_bf16(acc1[2 * j + 1], aq, bk + 2);
            }
        }

        // mma2: acc2 += counts @ v  (16 x 96, K=128) — P stays in registers
#pragma unroll
        for (int kk = 0; kk < 8; kk++) {
            uint32_t af[4];
            af[0] = pack_bf16x2(acc1[2 * kk][0], acc1[2 * kk][1]);
            af[1] = pack_bf16x2(acc1[2 * kk][2], acc1[2 * kk][3]);
            af[2] = pack_bf16x2(acc1[2 * kk + 1][0], acc1[2 * kk + 1][1]);
            af[3] = pack_bf16x2(acc1[2 * kk + 1][2], acc1[2 * kk + 1][3]);
#pragma unroll
            for (int g = 0; g < 6; g++) {
                uint32_t bv[4];
                ldsm_x4_t(bv, v_stage[st] + kk * (16 * 208) + g * 32);
                mma_bf16(acc2[2 * g], af, bv);
                mma_bf16(acc2[2 * g + 1], af, bv + 2);
            }
        }
        __syncthreads();
    }

    // epilogue: scale by 0.1, hi/lo split for the wo GEMM
#pragma unroll
    for (int nt = 0; nt < 12; nt++) {
        int r = rowbase + qb * 128 + wm + gid;
        int cb = qcol + nt * 8 + tig * 2;
#pragma unroll
        for (int half = 0; half < 2; half++) {
            int rr = r + half * 8;
            float v0 = 0.1f * acc2[nt][half * 2 + 0];
            float v1 = 0.1f * acc2[nt][half * 2 + 1];
            __nv_bfloat162 hi2, lo2;
            hi2.x = __float2bfloat16(v0);
            hi2.y = __float2bfloat16(v1);
            lo2.x = __float2bfloat16(v0 - __bfloat162float(hi2.x));
            lo2.y = __float2bfloat16(v1 - __bfloat162float(hi2.y));
            *(__nv_bfloat162*)(g_ahi + (size_t)rr * D_ + cb) = hi2;
            *(__nv_bfloat162*)(g_alo + (size_t)rr * D_ + cb) = lo2;
        }
    }
}

// ---------------- kernel 5: output GEMM  d_out = attn @ wo^T ----------------
// r8 (WIN): cp.async.ca double buffer; A/B hi/lo -> 3 MMAs per k-step.
#define WSTGB (4 * PTILEB)     // 40960
__global__ void __launch_bounds__(256)
gemm_wo_k(float* __restrict__ out) {
    extern __shared__ __nv_bfloat16 smw[];
    uint32_t sbase = smem_u32(smw);
    int tid = threadIdx.x;
    int lane = tid & 31, warp = tid >> 5;
    int gid = lane >> 2, tig = lane & 3;
    int wm = (warp >> 2) * 64, wn = (warp & 3) * 32;
    int m0 = blockIdx.y * 128, n0 = blockIdx.x * 128;

    uint32_t a_off = (wm + (lane & 15)) * PSTRB + (lane >> 4) * 16;
    uint32_t b_off = (wn + ((lane >> 4) << 3) + (lane & 7)) * PSTRB + ((lane >> 3) & 1) * 16;

    float acc[4][4][4];
#pragma unroll
    for (int a = 0; a < 4; a++)
#pragma unroll
        for (int b = 0; b < 4; b++)
#pragma unroll
            for (int c = 0; c < 4; c++) acc[a][b][c] = 0.f;

    int r0 = tid >> 2, c4b = (tid & 3) * 16;

#pragma unroll
    for (int it = 0; it < 2; it++) {
        int rr = r0 + it * 64;
        cpa16(sbase + rr * PSTRB + c4b,
              (const char*)(g_ahi + (size_t)(m0 + rr) * D_) + c4b);
        cpa16(sbase + PTILEB + rr * PSTRB + c4b,
              (const char*)(g_alo + (size_t)(m0 + rr) * D_) + c4b);
        cpa16(sbase + 2 * PTILEB + rr * PSTRB + c4b,
              (const char*)(g_WOhi + (size_t)(n0 + rr) * D_) + c4b);
        cpa16(sbase + 3 * PTILEB + rr * PSTRB + c4b,
              (const char*)(g_WOlo + (size_t)(n0 + rr) * D_) + c4b);
    }
    CP_COMMIT();

    for (int c = 0; c < NCH; c++) {
        if (c + 1 < NCH) {
            uint32_t st = ((c + 1) & 1) * WSTGB;
            int kb = (c + 1) * 64;
#pragma unroll
            for (int it = 0; it < 2; it++) {
                int rr = r0 + it * 64;
                cpa16(sbase + st + rr * PSTRB + c4b,
                      (const char*)(g_ahi + (size_t)(m0 + rr) * D_) + kb + c4b);
                cpa16(sbase + st + PTILEB + rr * PSTRB + c4b,
                      (const char*)(g_alo + (size_t)(m0 + rr) * D_) + kb + c4b);
                cpa16(sbase + st + 2 * PTILEB + rr * PSTRB + c4b,
                      (const char*)(g_WOhi + (size_t)(n0 + rr) * D_) + kb + c4b);
                cpa16(sbase + st + 3 * PTILEB + rr * PSTRB + c4b,
                      (const char*)(g_WOlo + (size_t)(n0 + rr) * D_) + kb + c4b);
            }
            CP_COMMIT();
            CP_WAIT(1);
        } else {
            CP_WAIT(0);
        }
        __syncthreads();
        uint32_t off = (c & 1) * WSTGB;
        uint32_t ah_base = sbase + off + a_off;
        uint32_t al_base = sbase + off + PTILEB + a_off;
        uint32_t bh_base = sbase + off + 2 * PTILEB + b_off;
        uint32_t bl_base = sbase + off + 3 * PTILEB + b_off;
#pragma unroll
        for (int kk = 0; kk < 2; kk++) {
            uint32_t afh[4][4], afl[4][4], bh[2][4], bl[2][4];
#pragma unroll
            for (int mt = 0; mt < 4; mt++) {
                ldsm_x4(afh[mt], ah_base + mt * (16 * PSTRB) + kk * 32);
                ldsm_x4(afl[mt], al_base + mt * (16 * PSTRB) + kk * 32);
            }
#pragma unroll
            for (int j = 0; j < 2; j++) {
                ldsm_x4(bh[j], bh_base + j * (16 * PSTRB) + kk * 32);
                ldsm_x4(bl[j], bl_base + j * (16 * PSTRB) + kk * 32);
            }
#pragma unroll
            for (int nt = 0; nt < 4; nt++) {
                const uint32_t* bhp = &bh[nt >> 1][(nt & 1) * 2];
                const uint32_t* blp = &bl[nt >> 1][(nt & 1) * 2];
#pragma unroll
                for (int mt = 0; mt < 4; mt++) {
                    mma_bf16(acc[mt][nt], afh[mt], bhp);
                    mma_bf16(acc[mt][nt], afh[mt], blp);
                    mma_bf16(acc[mt][nt], afl[mt], bhp);
                }
            }
        }
        __syncthreads();
    }
#pragma unroll
    for (int mt = 0; mt < 4; mt++)
#pragma unroll
        for (int nt = 0; nt < 4; nt++) {
            int r = m0 + wm + mt * 16 + gid;
            int c = n0 + wn + nt * 8 + tig * 2;
            *(float2*)(out + (size_t)r * D_ + c) = make_float2(acc[mt][nt][0], acc[mt][nt][1]);
            *(float2*)(out + (size_t)(r + 8) * D_ + c) = make_float2(acc[mt][nt][2], acc[mt][nt][3]);
        }
}

// ---------------- launch ----------------
extern "C" void kernel_launch(void* const* d_in, const int* in_sizes, int n_in,
                              void* d_out, int out_size) {
    (void)in_sizes; (void)n_in; (void)out_size;
    const float* x   = (const float*)d_in[0];
    const float* qw  = (const float*)d_in[1];
    const float* kw  = (const float*)d_in[2];
    const float* vw  = (const float*)d_in[3];
    const float* wow = (const float*)d_in[4];
    float* out = (float*)d_out;

    const int PROJ_SMEM = 2 * PSTGB;   // 61440
    const int WO_SMEM   = 2 * WSTGB;   // 81920
    cudaFuncSetAttribute(attn_k, cudaFuncAttributeMaxDynamicSharedMemorySize, ATTN_SMEM_B);
    cudaFuncSetAttribute(gemm_proj_fused, cudaFuncAttributeMaxDynamicSharedMemorySize, PROJ_SMEM);
    cudaFuncSetAttribute(gemm_wo_k, cudaFuncAttributeMaxDynamicSharedMemorySize, WO_SMEM);

    pack_w_k<<<(NCAT_ * D_ + 255) / 256, 256>>>(qw, kw, vw, wow);
    lif_x_k<<<(BCD_ + 255) / 256, 256>>>(x);
    gemm_proj_fused<<<dim3(NCAT_ / 128, BC_ / 128), 256, PROJ_SMEM>>>();
    attn_k<<<dim3(C_ / 128, T_ * B_ * H_), 256, ATTN_SMEM_B>>>();
    gemm_wo_k<<<dim3(D_ / 128, M_ / 128), 256, WO_SMEM>>>(out);
}